// round 1
// baseline (speedup 1.0000x reference)
#include <cuda_runtime.h>
#include <math.h>

#define N_TOK 2048
#define DM 256
#define PWY 4096
#define KSEL 4
#define NE 16
#define HMAX 1280
#define NPAIR (N_TOK*KSEL)

// ---------------- device scratch (static, no allocation) ----------------
__device__ float g_h1[N_TOK*256];
__device__ float g_h2[N_TOK*128];
__device__ float g_scores[N_TOK*PWY];
__device__ float g_rowmax[N_TOK];
__device__ float g_rowsuminv[N_TOK];
__device__ float g_freq[PWY];
__device__ int   g_topidx[NPAIR];
__device__ float g_topval[NPAIR];
__device__ int   g_cnt[3*NE];
__device__ int   g_list[3*NE*NPAIR];
__device__ float g_xpre[NPAIR*DM];
__device__ float g_xmid[(size_t)NPAIR*HMAX];
__device__ float g_xmlp[NPAIR*DM];

__device__ __forceinline__ float geluf(float v){
    return 0.5f*v*(1.0f+erff(v*0.70710678118654752f));
}

// ---------------- generic plain GEMM 64x64x16, 4x4 micro ----------------
__global__ __launch_bounds__(256) void gemm_plain(
    const float* __restrict__ A, const float* __restrict__ W,
    const float* __restrict__ bias, float* __restrict__ C,
    int M, int Nc, int Ka, int act)
{
    __shared__ float As[16][64];
    __shared__ float Ws[16][64];
    int tid = threadIdx.x;
    int m0 = blockIdx.y*64, n0 = blockIdx.x*64;
    int tx = tid & 15, ty = tid >> 4;
    int lr = tid >> 2, lk = (tid & 3)*4;
    int wr = tid >> 4, wc = (tid & 15)*4;
    float acc[4][4] = {};
    for (int k0 = 0; k0 < Ka; k0 += 16) {
        float4 av = *(const float4*)&A[(size_t)(m0+lr)*Ka + k0 + lk];
        As[lk+0][lr]=av.x; As[lk+1][lr]=av.y; As[lk+2][lr]=av.z; As[lk+3][lr]=av.w;
        *(float4*)&Ws[wr][wc] = *(const float4*)&W[(size_t)(k0+wr)*Nc + n0 + wc];
        __syncthreads();
#pragma unroll
        for (int kk = 0; kk < 16; kk++) {
            float4 a4 = *(const float4*)&As[kk][ty*4];
            float4 b4 = *(const float4*)&Ws[kk][tx*4];
            float aa[4]={a4.x,a4.y,a4.z,a4.w};
            float bb[4]={b4.x,b4.y,b4.z,b4.w};
#pragma unroll
            for (int i=0;i<4;i++)
#pragma unroll
                for (int j=0;j<4;j++) acc[i][j] += aa[i]*bb[j];
        }
        __syncthreads();
    }
#pragma unroll
    for (int i=0;i<4;i++){
        int r = m0 + ty*4 + i;
#pragma unroll
        for (int j=0;j<4;j++){
            int c = n0 + tx*4 + j;
            float v = acc[i][j] + bias[c];
            if (act==1) v = geluf(v);
            C[(size_t)r*Nc + c] = v;
        }
    }
}

// ---------------- softmax + topk + pathway_weights row ----------------
__global__ __launch_bounds__(256) void softmax_topk(
    const float* __restrict__ temp, float* __restrict__ pwout)
{
    __shared__ float s[PWY];
    __shared__ float red[256];
    __shared__ int   redi[256];
    __shared__ int   sel[KSEL];
    __shared__ float pv[KSEL];
    int n = blockIdx.x, tid = threadIdx.x;
    const float* srow = g_scores + (size_t)n*PWY;
    for (int i=0;i<4;i++){
        int idx = i*1024 + tid*4;
        *(float4*)&s[idx] = *(const float4*)&srow[idx];
    }
    __syncthreads();
    float invt = 1.0f/temp[0];

    // no-temp max
    float lm = -INFINITY;
    for (int i=0;i<16;i++) lm = fmaxf(lm, s[tid + i*256]);
    red[tid]=lm; __syncthreads();
    for (int off=128;off>0;off>>=1){ if(tid<off) red[tid]=fmaxf(red[tid],red[tid+off]); __syncthreads(); }
    float m0 = red[0]; __syncthreads();
    // no-temp sum
    float ls=0.f;
    for (int i=0;i<16;i++) ls += expf(s[tid+i*256]-m0);
    red[tid]=ls; __syncthreads();
    for (int off=128;off>0;off>>=1){ if(tid<off) red[tid]+=red[tid+off]; __syncthreads(); }
    float sum0 = red[0]; __syncthreads();
    if (tid==0){ g_rowmax[n]=m0; g_rowsuminv[n]=1.0f/sum0; }

    // temp-scaled max
    float lmt = -INFINITY;
    for (int i=0;i<16;i++) lmt = fmaxf(lmt, s[tid+i*256]*invt);
    red[tid]=lmt; __syncthreads();
    for (int off=128;off>0;off>>=1){ if(tid<off) red[tid]=fmaxf(red[tid],red[tid+off]); __syncthreads(); }
    float mt = red[0]; __syncthreads();
    // temp-scaled sum
    float lst=0.f;
    for (int i=0;i<16;i++) lst += expf(s[tid+i*256]*invt - mt);
    red[tid]=lst; __syncthreads();
    for (int off=128;off>0;off>>=1){ if(tid<off) red[tid]+=red[tid+off]; __syncthreads(); }
    float invsumt = 1.0f/red[0]; __syncthreads();

    // top-4: iterative argmax with exclusion, lowest-index tie break
    for (int t=0;t<KSEL;t++){
        float bv=-INFINITY; int bi=PWY;
        for (int i=0;i<16;i++){
            int j = tid + i*256;
            bool skip=false;
            for (int u=0;u<t;u++) if (sel[u]==j) skip=true;
            if (!skip){
                float v = s[j]*invt;
                if (v>bv || (v==bv && j<bi)){ bv=v; bi=j; }
            }
        }
        red[tid]=bv; redi[tid]=bi; __syncthreads();
        for (int off=128;off>0;off>>=1){
            if (tid<off){
                float ov=red[tid+off]; int oi=redi[tid+off];
                if (ov>red[tid] || (ov==red[tid] && oi<redi[tid])){ red[tid]=ov; redi[tid]=oi; }
            }
            __syncthreads();
        }
        if (tid==0) sel[t]=redi[0];
        __syncthreads();
    }

    if (tid < KSEL) pv[tid] = expf(s[sel[tid]]*invt - mt)*invsumt;
    __syncthreads();
    float psum = pv[0]+pv[1]+pv[2]+pv[3];
    float invps = 1.0f/(psum + 1e-8f);
    if (tid < KSEL){
        g_topidx[n*KSEL+tid] = sel[tid];
        g_topval[n*KSEL+tid] = pv[tid];
    }
    float* prow = pwout + (size_t)n*PWY;
    for (int i=0;i<16;i++){
        int j = tid + i*256;
        float v = 0.f;
#pragma unroll
        for (int t=0;t<KSEL;t++) if (j==sel[t]) v = pv[t]*invps;
        prow[j] = v;
    }
}

// ---------------- freq (column sums of no-temp softmax) ----------------
__global__ __launch_bounds__(256) void freq_partial()
{
    int p = blockIdx.x*256 + threadIdx.x;
    int nbeg = blockIdx.y*256;
    float acc = 0.f;
    for (int n=nbeg; n<nbeg+256; n++)
        acc += expf(g_scores[(size_t)n*PWY + p] - g_rowmax[n]) * g_rowsuminv[n];
    atomicAdd(&g_freq[p], acc);
}

__global__ __launch_bounds__(256) void glbl_loss_kernel(float* __restrict__ out)
{
    __shared__ float red[256];
    int tid = threadIdx.x;
    const float invN = 1.0f/(float)N_TOK;
    float lsum = 0.f;
    for (int i=0;i<PWY/256;i++) lsum += g_freq[tid+i*256]*invN;
    red[tid]=lsum; __syncthreads();
    for (int off=128;off>0;off>>=1){ if(tid<off) red[tid]+=red[tid+off]; __syncthreads(); }
    float mean = red[0]/(float)PWY; __syncthreads();
    float lss = 0.f;
    for (int i=0;i<PWY/256;i++){
        float d = g_freq[tid+i*256]*invN - mean;
        lss += d*d;
    }
    red[tid]=lss; __syncthreads();
    for (int off=128;off>0;off>>=1){ if(tid<off) red[tid]+=red[tid+off]; __syncthreads(); }
    if (tid==0) out[0] = (float)PWY * (red[0]/(float)(PWY-1));
}

// ---------------- routing lists ----------------
__global__ __launch_bounds__(256) void build_lists()
{
    int i = blockIdx.x*256 + threadIdx.x;
    if (i >= NPAIR) return;
    int idx = g_topidx[i];
    int pe = idx >> 8, rem = idx & 255;
    int me = rem >> 4, qe = rem & 15;
    int pos;
    pos = atomicAdd(&g_cnt[pe], 1);         g_list[pe*NPAIR + pos] = i;
    pos = atomicAdd(&g_cnt[NE+me], 1);      g_list[(NE+me)*NPAIR + pos] = i;
    pos = atomicAdd(&g_cnt[2*NE+qe], 1);    g_list[(2*NE+qe)*NPAIR + pos] = i;
}

// ---------------- pre experts: gathered GEMM + LN + act, full 256-col row ----------------
__global__ __launch_bounds__(256) void pre_expert(
    const float* __restrict__ x, const float* __restrict__ pwgt,
    const float* __restrict__ pb, const float* __restrict__ pg,
    const float* __restrict__ pbb)
{
    int e = blockIdx.y;
    int cnt = g_cnt[e];
    int m0 = blockIdx.x*64;
    if (m0 >= cnt) return;
    const int* list = g_list + e*NPAIR;
    __shared__ int pairs[64];
    __shared__ float As[16][64];
    __shared__ float Ws[16][256];
    int tid = threadIdx.x;
    if (tid < 64) pairs[tid] = (m0+tid < cnt) ? list[m0+tid] : -1;
    __syncthreads();
    int tx = tid & 15, ry = tid >> 4;
    int lr = tid >> 2, lk = (tid & 3)*4;
    const float* Wg = pwgt + (size_t)e*DM*DM;
    float acc[4][16] = {};
    for (int k0=0;k0<DM;k0+=16){
        int pr = pairs[lr];
        float4 av = make_float4(0.f,0.f,0.f,0.f);
        if (pr >= 0) av = *(const float4*)&x[(size_t)(pr>>2)*DM + k0 + lk];
        As[lk+0][lr]=av.x; As[lk+1][lr]=av.y; As[lk+2][lr]=av.z; As[lk+3][lr]=av.w;
#pragma unroll
        for (int jj=0;jj<4;jj++){
            int idx = jj*1024 + tid*4;
            int kr = idx >> 8, c = idx & 255;
            *(float4*)&Ws[kr][c] = *(const float4*)&Wg[(size_t)(k0+kr)*DM + c];
        }
        __syncthreads();
#pragma unroll
        for (int kk=0;kk<16;kk++){
            float4 a4 = *(const float4*)&As[kk][ry*4];
            float aa[4]={a4.x,a4.y,a4.z,a4.w};
#pragma unroll
            for (int j4=0;j4<4;j4++){
                float4 b4 = *(const float4*)&Ws[kk][tx*16 + j4*4];
                float bb[4]={b4.x,b4.y,b4.z,b4.w};
#pragma unroll
                for (int i=0;i<4;i++)
#pragma unroll
                    for (int j=0;j<4;j++) acc[i][j4*4+j] += aa[i]*bb[j];
            }
        }
        __syncthreads();
    }
    int actm = e % 3;
#pragma unroll
    for (int i=0;i<4;i++){
        int r = ry*4 + i;
        int pr = pairs[r];
        float y[16];
        float lsum = 0.f;
#pragma unroll
        for (int j=0;j<16;j++){
            y[j] = acc[i][j] + pb[e*DM + tx*16 + j];
            lsum += y[j];
        }
#pragma unroll
        for (int m=8;m>0;m>>=1) lsum += __shfl_xor_sync(0xffffffffu, lsum, m, 32);
        float mu = lsum * (1.0f/DM);
        float lss = 0.f;
#pragma unroll
        for (int j=0;j<16;j++){ float d=y[j]-mu; lss += d*d; }
#pragma unroll
        for (int m=8;m>0;m>>=1) lss += __shfl_xor_sync(0xffffffffu, lss, m, 32);
        float rstd = rsqrtf(lss*(1.0f/DM) + 1e-5f);
        if (pr >= 0){
            float* orow = g_xpre + (size_t)pr*DM;
#pragma unroll
            for (int j=0;j<16;j++){
                int c = tx*16 + j;
                float v = (y[j]-mu)*rstd*pg[e*DM+c] + pbb[e*DM+c];
                v = (actm==0) ? geluf(v) : (actm==1) ? fmaxf(v,0.f) : tanhf(v);
                orow[c] = v;
            }
        }
    }
}

// ---------------- MLP stage 1: gathered GEMM + act (variable hidden) ----------------
__global__ __launch_bounds__(256) void mlp1_gemm(
    const float* __restrict__ mw1, const float* __restrict__ mb1)
{
    int e = blockIdx.z;
    int hid = DM*(2 + (e>>2));
    int n0 = blockIdx.x*64;
    if (n0 >= hid) return;
    int cnt = g_cnt[NE+e];
    int m0 = blockIdx.y*64;
    if (m0 >= cnt) return;
    const int* list = g_list + (NE+e)*NPAIR;
    __shared__ int pairs[64];
    __shared__ float As[16][64];
    __shared__ float Ws[16][64];
    int tid = threadIdx.x;
    if (tid < 64) pairs[tid] = (m0+tid < cnt) ? list[m0+tid] : -1;
    __syncthreads();
    int tx = tid & 15, ty = tid >> 4;
    int lr = tid >> 2, lk = (tid & 3)*4;
    int wr = tid >> 4, wc = (tid & 15)*4;
    const float* Wg = mw1 + (size_t)e*DM*HMAX;
    float acc[4][4] = {};
    for (int k0=0;k0<DM;k0+=16){
        int pr = pairs[lr];
        float4 av = make_float4(0.f,0.f,0.f,0.f);
        if (pr >= 0) av = *(const float4*)&g_xpre[(size_t)pr*DM + k0 + lk];
        As[lk+0][lr]=av.x; As[lk+1][lr]=av.y; As[lk+2][lr]=av.z; As[lk+3][lr]=av.w;
        *(float4*)&Ws[wr][wc] = *(const float4*)&Wg[(size_t)(k0+wr)*HMAX + n0 + wc];
        __syncthreads();
#pragma unroll
        for (int kk=0;kk<16;kk++){
            float4 a4 = *(const float4*)&As[kk][ty*4];
            float4 b4 = *(const float4*)&Ws[kk][tx*4];
            float aa[4]={a4.x,a4.y,a4.z,a4.w};
            float bb[4]={b4.x,b4.y,b4.z,b4.w};
#pragma unroll
            for (int i=0;i<4;i++)
#pragma unroll
                for (int j=0;j<4;j++) acc[i][j] += aa[i]*bb[j];
        }
        __syncthreads();
    }
    bool use_gelu = ((e & 1) == 0);
#pragma unroll
    for (int i=0;i<4;i++){
        int r = ty*4 + i;
        int pr = pairs[r];
        if (pr < 0) continue;
#pragma unroll
        for (int j=0;j<4;j++){
            int c = n0 + tx*4 + j;
            float v = acc[i][j] + mb1[e*HMAX + c];
            v = use_gelu ? geluf(v) : fmaxf(v, 0.f);
            g_xmid[(size_t)pr*HMAX + c] = v;
        }
    }
}

// ---------------- MLP stage 2 ----------------
__global__ __launch_bounds__(256) void mlp2_gemm(
    const float* __restrict__ mw2, const float* __restrict__ mb2)
{
    int e = blockIdx.z;
    int hid = DM*(2 + (e>>2));
    int n0 = blockIdx.x*64;
    int cnt = g_cnt[NE+e];
    int m0 = blockIdx.y*64;
    if (m0 >= cnt) return;
    const int* list = g_list + (NE+e)*NPAIR;
    __shared__ int pairs[64];
    __shared__ float As[16][64];
    __shared__ float Ws[16][64];
    int tid = threadIdx.x;
    if (tid < 64) pairs[tid] = (m0+tid < cnt) ? list[m0+tid] : -1;
    __syncthreads();
    int tx = tid & 15, ty = tid >> 4;
    int lr = tid >> 2, lk = (tid & 3)*4;
    int wr = tid >> 4, wc = (tid & 15)*4;
    const float* Wg = mw2 + (size_t)e*HMAX*DM;
    float acc[4][4] = {};
    for (int k0=0;k0<hid;k0+=16){
        int pr = pairs[lr];
        float4 av = make_float4(0.f,0.f,0.f,0.f);
        if (pr >= 0) av = *(const float4*)&g_xmid[(size_t)pr*HMAX + k0 + lk];
        As[lk+0][lr]=av.x; As[lk+1][lr]=av.y; As[lk+2][lr]=av.z; As[lk+3][lr]=av.w;
        *(float4*)&Ws[wr][wc] = *(const float4*)&Wg[(size_t)(k0+wr)*DM + n0 + wc];
        __syncthreads();
#pragma unroll
        for (int kk=0;kk<16;kk++){
            float4 a4 = *(const float4*)&As[kk][ty*4];
            float4 b4 = *(const float4*)&Ws[kk][tx*4];
            float aa[4]={a4.x,a4.y,a4.z,a4.w};
            float bb[4]={b4.x,b4.y,b4.z,b4.w};
#pragma unroll
            for (int i=0;i<4;i++)
#pragma unroll
                for (int j=0;j<4;j++) acc[i][j] += aa[i]*bb[j];
        }
        __syncthreads();
    }
#pragma unroll
    for (int i=0;i<4;i++){
        int r = ty*4 + i;
        int pr = pairs[r];
        if (pr < 0) continue;
#pragma unroll
        for (int j=0;j<4;j++){
            int c = n0 + tx*4 + j;
            g_xmlp[(size_t)pr*DM + c] = acc[i][j] + mb2[e*DM + c];
        }
    }
}

// ---------------- post experts: gathered GEMM + optional LN + weighted scatter ----------------
__global__ __launch_bounds__(256) void post_expert(
    const float* __restrict__ qw, const float* __restrict__ qb,
    const float* __restrict__ qg, const float* __restrict__ qbb,
    float* __restrict__ out_y)
{
    int e = blockIdx.y;
    int cnt = g_cnt[2*NE+e];
    int m0 = blockIdx.x*64;
    if (m0 >= cnt) return;
    const int* list = g_list + (2*NE+e)*NPAIR;
    __shared__ int pairs[64];
    __shared__ float As[16][64];
    __shared__ float Ws[16][256];
    int tid = threadIdx.x;
    if (tid < 64) pairs[tid] = (m0+tid < cnt) ? list[m0+tid] : -1;
    __syncthreads();
    int tx = tid & 15, ry = tid >> 4;
    int lr = tid >> 2, lk = (tid & 3)*4;
    const float* Wg = qw + (size_t)e*DM*DM;
    float acc[4][16] = {};
    for (int k0=0;k0<DM;k0+=16){
        int pr = pairs[lr];
        float4 av = make_float4(0.f,0.f,0.f,0.f);
        if (pr >= 0) av = *(const float4*)&g_xmlp[(size_t)pr*DM + k0 + lk];
        As[lk+0][lr]=av.x; As[lk+1][lr]=av.y; As[lk+2][lr]=av.z; As[lk+3][lr]=av.w;
#pragma unroll
        for (int jj=0;jj<4;jj++){
            int idx = jj*1024 + tid*4;
            int kr = idx >> 8, c = idx & 255;
            *(float4*)&Ws[kr][c] = *(const float4*)&Wg[(size_t)(k0+kr)*DM + c];
        }
        __syncthreads();
#pragma unroll
        for (int kk=0;kk<16;kk++){
            float4 a4 = *(const float4*)&As[kk][ry*4];
            float aa[4]={a4.x,a4.y,a4.z,a4.w};
#pragma unroll
            for (int j4=0;j4<4;j4++){
                float4 b4 = *(const float4*)&Ws[kk][tx*16 + j4*4];
                float bb[4]={b4.x,b4.y,b4.z,b4.w};
#pragma unroll
                for (int i=0;i<4;i++)
#pragma unroll
                    for (int j=0;j<4;j++) acc[i][j4*4+j] += aa[i]*bb[j];
            }
        }
        __syncthreads();
    }
    bool do_ln = ((e & 1) == 0);
#pragma unroll
    for (int i=0;i<4;i++){
        int r = ry*4 + i;
        int pr = pairs[r];
        float y[16];
#pragma unroll
        for (int j=0;j<16;j++) y[j] = acc[i][j] + qb[e*DM + tx*16 + j];
        if (do_ln){
            float lsum = 0.f;
#pragma unroll
            for (int j=0;j<16;j++) lsum += y[j];
#pragma unroll
            for (int m=8;m>0;m>>=1) lsum += __shfl_xor_sync(0xffffffffu, lsum, m, 32);
            float mu = lsum * (1.0f/DM);
            float lss = 0.f;
#pragma unroll
            for (int j=0;j<16;j++){ float d=y[j]-mu; lss += d*d; }
#pragma unroll
            for (int m=8;m>0;m>>=1) lss += __shfl_xor_sync(0xffffffffu, lss, m, 32);
            float rstd = rsqrtf(lss*(1.0f/DM) + 1e-5f);
#pragma unroll
            for (int j=0;j<16;j++){
                int c = tx*16 + j;
                y[j] = (y[j]-mu)*rstd*qg[e*DM+c] + qbb[e*DM+c];
            }
        }
        if (pr >= 0){
            float w = g_topval[pr];
            int tok = pr >> 2;
#pragma unroll
            for (int j=0;j<16;j++){
                int c = tx*16 + j;
                atomicAdd(&out_y[(size_t)tok*DM + c], y[j]*w);
            }
        }
    }
}

// ---------------- host launch ----------------
extern "C" void kernel_launch(void* const* d_in, const int* in_sizes, int n_in,
                              void* d_out, int out_size)
{
    const float* x   = (const float*)d_in[0];
    const float* rw1 = (const float*)d_in[1];
    const float* rb1 = (const float*)d_in[2];
    const float* rw2 = (const float*)d_in[3];
    const float* rb2 = (const float*)d_in[4];
    const float* rw3 = (const float*)d_in[5];
    const float* rb3 = (const float*)d_in[6];
    const float* temp= (const float*)d_in[7];
    const float* pw  = (const float*)d_in[8];
    const float* pb  = (const float*)d_in[9];
    const float* pg  = (const float*)d_in[10];
    const float* pbb = (const float*)d_in[11];
    const float* mw1 = (const float*)d_in[12];
    const float* mb1 = (const float*)d_in[13];
    const float* mw2 = (const float*)d_in[14];
    const float* mb2 = (const float*)d_in[15];
    const float* qw  = (const float*)d_in[16];
    const float* qb  = (const float*)d_in[17];
    const float* qg  = (const float*)d_in[18];
    const float* qbb = (const float*)d_in[19];

    float* out      = (float*)d_out;
    float* out_y    = out;                     // [N_TOK*DM]
    float* out_loss = out + N_TOK*DM;          // [1]
    float* out_pw   = out + N_TOK*DM + 1;      // [N_TOK*PWY]

    void* p;
    cudaGetSymbolAddress(&p, g_h1);     float* h1 = (float*)p;
    cudaGetSymbolAddress(&p, g_h2);     float* h2 = (float*)p;
    cudaGetSymbolAddress(&p, g_scores); float* scores = (float*)p;
    cudaGetSymbolAddress(&p, g_freq);   float* freqp = (float*)p;
    cudaGetSymbolAddress(&p, g_cnt);    int*   cntp = (int*)p;

    cudaMemsetAsync(out_y, 0, (size_t)N_TOK*DM*sizeof(float), 0);
    cudaMemsetAsync(freqp, 0, PWY*sizeof(float), 0);
    cudaMemsetAsync(cntp,  0, 3*NE*sizeof(int), 0);

    // router
    gemm_plain<<<dim3(256/64, N_TOK/64), 256>>>(x,  rw1, rb1, h1,     N_TOK, 256,  256, 1);
    gemm_plain<<<dim3(128/64, N_TOK/64), 256>>>(h1, rw2, rb2, h2,     N_TOK, 128,  256, 1);
    gemm_plain<<<dim3(PWY/64, N_TOK/64), 256>>>(h2, rw3, rb3, scores, N_TOK, PWY,  128, 0);

    // softmax + topk + pathway weights (writes full rows, no memset needed)
    softmax_topk<<<N_TOK, 256>>>(temp, out_pw);

    // GLBL loss
    freq_partial<<<dim3(PWY/256, N_TOK/256), 256>>>();
    glbl_loss_kernel<<<1, 256>>>(out_loss);

    // routing
    build_lists<<<NPAIR/256, 256>>>();

    // experts
    pre_expert<<<dim3(NPAIR/64, NE), 256>>>(x, pw, pb, pg, pbb);
    mlp1_gemm<<<dim3(HMAX/64, NPAIR/64, NE), 256>>>(mw1, mb1);
    mlp2_gemm<<<dim3(DM/64, NPAIR/64, NE), 256>>>(mw2, mb2);
    post_expert<<<dim3(NPAIR/64, NE), 256>>>(qw, qb, qg, qbb, out_y);
}

// round 2
// speedup vs baseline: 1.0039x; 1.0039x over previous
#include <cuda_runtime.h>
#include <math.h>

#define N_TOK 2048
#define DM 256
#define PWY 4096
#define KSEL 4
#define NE 16
#define HMAX 1280
#define NPAIR (N_TOK*KSEL)

// ---------------- device scratch (static, no allocation) ----------------
__device__ float g_h1[N_TOK*256];
__device__ float g_h2[N_TOK*128];
__device__ float g_scores[N_TOK*PWY];
__device__ float g_rowmax[N_TOK];
__device__ float g_rowsuminv[N_TOK];
__device__ float g_freq[PWY];
__device__ int   g_topidx[NPAIR];
__device__ float g_topval[NPAIR];
__device__ int   g_cnt[3*NE];
__device__ int   g_list[3*NE*NPAIR];
__device__ float g_xpre[NPAIR*DM];
__device__ float g_xmid[(size_t)NPAIR*HMAX];
__device__ float g_xmlp[NPAIR*DM];

__device__ __forceinline__ float geluf(float v){
    return 0.5f*v*(1.0f+erff(v*0.70710678118654752f));
}

// ---------------- generic plain GEMM 64x64x16, 4x4 micro ----------------
__global__ __launch_bounds__(256) void gemm_plain(
    const float* __restrict__ A, const float* __restrict__ W,
    const float* __restrict__ bias, float* __restrict__ C,
    int M, int Nc, int Ka, int act)
{
    __shared__ float As[16][64];
    __shared__ float Ws[16][64];
    int tid = threadIdx.x;
    int m0 = blockIdx.y*64, n0 = blockIdx.x*64;
    int tx = tid & 15, ty = tid >> 4;
    int lr = tid >> 2, lk = (tid & 3)*4;
    int wr = tid >> 4, wc = (tid & 15)*4;
    float acc[4][4] = {};
    for (int k0 = 0; k0 < Ka; k0 += 16) {
        float4 av = *(const float4*)&A[(size_t)(m0+lr)*Ka + k0 + lk];
        As[lk+0][lr]=av.x; As[lk+1][lr]=av.y; As[lk+2][lr]=av.z; As[lk+3][lr]=av.w;
        *(float4*)&Ws[wr][wc] = *(const float4*)&W[(size_t)(k0+wr)*Nc + n0 + wc];
        __syncthreads();
#pragma unroll
        for (int kk = 0; kk < 16; kk++) {
            float4 a4 = *(const float4*)&As[kk][ty*4];
            float4 b4 = *(const float4*)&Ws[kk][tx*4];
            float aa[4]={a4.x,a4.y,a4.z,a4.w};
            float bb[4]={b4.x,b4.y,b4.z,b4.w};
#pragma unroll
            for (int i=0;i<4;i++)
#pragma unroll
                for (int j=0;j<4;j++) acc[i][j] += aa[i]*bb[j];
        }
        __syncthreads();
    }
#pragma unroll
    for (int i=0;i<4;i++){
        int r = m0 + ty*4 + i;
#pragma unroll
        for (int j=0;j<4;j++){
            int c = n0 + tx*4 + j;
            float v = acc[i][j] + bias[c];
            if (act==1) v = geluf(v);
            C[(size_t)r*Nc + c] = v;
        }
    }
}

// ---------------- softmax + topk + pathway_weights row ----------------
__global__ __launch_bounds__(256) void softmax_topk(
    const float* __restrict__ temp, float* __restrict__ pwout)
{
    __shared__ float s[PWY];
    __shared__ float red[256];
    __shared__ int   redi[256];
    __shared__ int   sel[KSEL];
    __shared__ float pv[KSEL];
    int n = blockIdx.x, tid = threadIdx.x;
    const float* srow = g_scores + (size_t)n*PWY;
    for (int i=0;i<4;i++){
        int idx = i*1024 + tid*4;
        *(float4*)&s[idx] = *(const float4*)&srow[idx];
    }
    __syncthreads();
    float invt = 1.0f/temp[0];

    // no-temp max
    float lm = -INFINITY;
    for (int i=0;i<16;i++) lm = fmaxf(lm, s[tid + i*256]);
    red[tid]=lm; __syncthreads();
    for (int off=128;off>0;off>>=1){ if(tid<off) red[tid]=fmaxf(red[tid],red[tid+off]); __syncthreads(); }
    float m0 = red[0]; __syncthreads();
    // no-temp sum
    float ls=0.f;
    for (int i=0;i<16;i++) ls += expf(s[tid+i*256]-m0);
    red[tid]=ls; __syncthreads();
    for (int off=128;off>0;off>>=1){ if(tid<off) red[tid]+=red[tid+off]; __syncthreads(); }
    float sum0 = red[0]; __syncthreads();
    if (tid==0){ g_rowmax[n]=m0; g_rowsuminv[n]=1.0f/sum0; }

    // temp-scaled max
    float lmt = -INFINITY;
    for (int i=0;i<16;i++) lmt = fmaxf(lmt, s[tid+i*256]*invt);
    red[tid]=lmt; __syncthreads();
    for (int off=128;off>0;off>>=1){ if(tid<off) red[tid]=fmaxf(red[tid],red[tid+off]); __syncthreads(); }
    float mt = red[0]; __syncthreads();
    // temp-scaled sum
    float lst=0.f;
    for (int i=0;i<16;i++) lst += expf(s[tid+i*256]*invt - mt);
    red[tid]=lst; __syncthreads();
    for (int off=128;off>0;off>>=1){ if(tid<off) red[tid]+=red[tid+off]; __syncthreads(); }
    float invsumt = 1.0f/red[0]; __syncthreads();

    // top-4: iterative argmax with exclusion, lowest-index tie break
    for (int t=0;t<KSEL;t++){
        float bv=-INFINITY; int bi=PWY;
        for (int i=0;i<16;i++){
            int j = tid + i*256;
            bool skip=false;
            for (int u=0;u<t;u++) if (sel[u]==j) skip=true;
            if (!skip){
                float v = s[j]*invt;
                if (v>bv || (v==bv && j<bi)){ bv=v; bi=j; }
            }
        }
        red[tid]=bv; redi[tid]=bi; __syncthreads();
        for (int off=128;off>0;off>>=1){
            if (tid<off){
                float ov=red[tid+off]; int oi=redi[tid+off];
                if (ov>red[tid] || (ov==red[tid] && oi<redi[tid])){ red[tid]=ov; redi[tid]=oi; }
            }
            __syncthreads();
        }
        if (tid==0) sel[t]=redi[0];
        __syncthreads();
    }

    if (tid < KSEL) pv[tid] = expf(s[sel[tid]]*invt - mt)*invsumt;
    __syncthreads();
    float psum = pv[0]+pv[1]+pv[2]+pv[3];
    float invps = 1.0f/(psum + 1e-8f);
    if (tid < KSEL){
        g_topidx[n*KSEL+tid] = sel[tid];
        g_topval[n*KSEL+tid] = pv[tid];
    }
    float* prow = pwout + (size_t)n*PWY;
    for (int i=0;i<16;i++){
        int j = tid + i*256;
        float v = 0.f;
#pragma unroll
        for (int t=0;t<KSEL;t++) if (j==sel[t]) v = pv[t]*invps;
        prow[j] = v;
    }
}

// ---------------- freq (column sums of no-temp softmax) ----------------
__global__ __launch_bounds__(256) void freq_partial()
{
    int p = blockIdx.x*256 + threadIdx.x;
    int nbeg = blockIdx.y*256;
    float acc = 0.f;
    for (int n=nbeg; n<nbeg+256; n++)
        acc += expf(g_scores[(size_t)n*PWY + p] - g_rowmax[n]) * g_rowsuminv[n];
    atomicAdd(&g_freq[p], acc);
}

__global__ __launch_bounds__(256) void glbl_loss_kernel(float* __restrict__ out)
{
    __shared__ float red[256];
    int tid = threadIdx.x;
    const float invN = 1.0f/(float)N_TOK;
    float lsum = 0.f;
    for (int i=0;i<PWY/256;i++) lsum += g_freq[tid+i*256]*invN;
    red[tid]=lsum; __syncthreads();
    for (int off=128;off>0;off>>=1){ if(tid<off) red[tid]+=red[tid+off]; __syncthreads(); }
    float mean = red[0]/(float)PWY; __syncthreads();
    float lss = 0.f;
    for (int i=0;i<PWY/256;i++){
        float d = g_freq[tid+i*256]*invN - mean;
        lss += d*d;
    }
    red[tid]=lss; __syncthreads();
    for (int off=128;off>0;off>>=1){ if(tid<off) red[tid]+=red[tid+off]; __syncthreads(); }
    if (tid==0) out[0] = (float)PWY * (red[0]/(float)(PWY-1));
}

// ---------------- routing lists ----------------
__global__ __launch_bounds__(256) void build_lists()
{
    int i = blockIdx.x*256 + threadIdx.x;
    if (i >= NPAIR) return;
    int idx = g_topidx[i];
    int pe = idx >> 8, rem = idx & 255;
    int me = rem >> 4, qe = rem & 15;
    int pos;
    pos = atomicAdd(&g_cnt[pe], 1);         g_list[pe*NPAIR + pos] = i;
    pos = atomicAdd(&g_cnt[NE+me], 1);      g_list[(NE+me)*NPAIR + pos] = i;
    pos = atomicAdd(&g_cnt[2*NE+qe], 1);    g_list[(2*NE+qe)*NPAIR + pos] = i;
}

// ---------------- pre experts: gathered GEMM + LN + act, full 256-col row ----------------
__global__ __launch_bounds__(256) void pre_expert(
    const float* __restrict__ x, const float* __restrict__ pwgt,
    const float* __restrict__ pb, const float* __restrict__ pg,
    const float* __restrict__ pbb)
{
    int e = blockIdx.y;
    int cnt = g_cnt[e];
    int m0 = blockIdx.x*64;
    if (m0 >= cnt) return;
    const int* list = g_list + e*NPAIR;
    __shared__ int pairs[64];
    __shared__ float As[16][64];
    __shared__ float Ws[16][256];
    int tid = threadIdx.x;
    if (tid < 64) pairs[tid] = (m0+tid < cnt) ? list[m0+tid] : -1;
    __syncthreads();
    int tx = tid & 15, ry = tid >> 4;
    int lr = tid >> 2, lk = (tid & 3)*4;
    const float* Wg = pwgt + (size_t)e*DM*DM;
    float acc[4][16] = {};
    for (int k0=0;k0<DM;k0+=16){
        int pr = pairs[lr];
        float4 av = make_float4(0.f,0.f,0.f,0.f);
        if (pr >= 0) av = *(const float4*)&x[(size_t)(pr>>2)*DM + k0 + lk];
        As[lk+0][lr]=av.x; As[lk+1][lr]=av.y; As[lk+2][lr]=av.z; As[lk+3][lr]=av.w;
#pragma unroll
        for (int jj=0;jj<4;jj++){
            int idx = jj*1024 + tid*4;
            int kr = idx >> 8, c = idx & 255;
            *(float4*)&Ws[kr][c] = *(const float4*)&Wg[(size_t)(k0+kr)*DM + c];
        }
        __syncthreads();
#pragma unroll
        for (int kk=0;kk<16;kk++){
            float4 a4 = *(const float4*)&As[kk][ry*4];
            float aa[4]={a4.x,a4.y,a4.z,a4.w};
#pragma unroll
            for (int j4=0;j4<4;j4++){
                float4 b4 = *(const float4*)&Ws[kk][tx*16 + j4*4];
                float bb[4]={b4.x,b4.y,b4.z,b4.w};
#pragma unroll
                for (int i=0;i<4;i++)
#pragma unroll
                    for (int j=0;j<4;j++) acc[i][j4*4+j] += aa[i]*bb[j];
            }
        }
        __syncthreads();
    }
    int actm = e % 3;
#pragma unroll
    for (int i=0;i<4;i++){
        int r = ry*4 + i;
        int pr = pairs[r];
        float y[16];
        float lsum = 0.f;
#pragma unroll
        for (int j=0;j<16;j++){
            y[j] = acc[i][j] + pb[e*DM + tx*16 + j];
            lsum += y[j];
        }
#pragma unroll
        for (int m=8;m>0;m>>=1) lsum += __shfl_xor_sync(0xffffffffu, lsum, m, 32);
        float mu = lsum * (1.0f/DM);
        float lss = 0.f;
#pragma unroll
        for (int j=0;j<16;j++){ float d=y[j]-mu; lss += d*d; }
#pragma unroll
        for (int m=8;m>0;m>>=1) lss += __shfl_xor_sync(0xffffffffu, lss, m, 32);
        float rstd = rsqrtf(lss*(1.0f/DM) + 1e-5f);
        if (pr >= 0){
            float* orow = g_xpre + (size_t)pr*DM;
#pragma unroll
            for (int j=0;j<16;j++){
                int c = tx*16 + j;
                float v = (y[j]-mu)*rstd*pg[e*DM+c] + pbb[e*DM+c];
                v = (actm==0) ? geluf(v) : (actm==1) ? fmaxf(v,0.f) : tanhf(v);
                orow[c] = v;
            }
        }
    }
}

// ---------------- MLP stage 1: gathered GEMM + act (variable hidden) ----------------
__global__ __launch_bounds__(256) void mlp1_gemm(
    const float* __restrict__ mw1, const float* __restrict__ mb1)
{
    int e = blockIdx.z;
    int hid = DM*(2 + (e>>2));
    int n0 = blockIdx.x*64;
    if (n0 >= hid) return;
    int cnt = g_cnt[NE+e];
    int m0 = blockIdx.y*64;
    if (m0 >= cnt) return;
    const int* list = g_list + (NE+e)*NPAIR;
    __shared__ int pairs[64];
    __shared__ float As[16][64];
    __shared__ float Ws[16][64];
    int tid = threadIdx.x;
    if (tid < 64) pairs[tid] = (m0+tid < cnt) ? list[m0+tid] : -1;
    __syncthreads();
    int tx = tid & 15, ty = tid >> 4;
    int lr = tid >> 2, lk = (tid & 3)*4;
    int wr = tid >> 4, wc = (tid & 15)*4;
    const float* Wg = mw1 + (size_t)e*DM*HMAX;
    float acc[4][4] = {};
    for (int k0=0;k0<DM;k0+=16){
        int pr = pairs[lr];
        float4 av = make_float4(0.f,0.f,0.f,0.f);
        if (pr >= 0) av = *(const float4*)&g_xpre[(size_t)pr*DM + k0 + lk];
        As[lk+0][lr]=av.x; As[lk+1][lr]=av.y; As[lk+2][lr]=av.z; As[lk+3][lr]=av.w;
        *(float4*)&Ws[wr][wc] = *(const float4*)&Wg[(size_t)(k0+wr)*HMAX + n0 + wc];
        __syncthreads();
#pragma unroll
        for (int kk=0;kk<16;kk++){
            float4 a4 = *(const float4*)&As[kk][ty*4];
            float4 b4 = *(const float4*)&Ws[kk][tx*4];
            float aa[4]={a4.x,a4.y,a4.z,a4.w};
            float bb[4]={b4.x,b4.y,b4.z,b4.w};
#pragma unroll
            for (int i=0;i<4;i++)
#pragma unroll
                for (int j=0;j<4;j++) acc[i][j] += aa[i]*bb[j];
        }
        __syncthreads();
    }
    bool use_gelu = ((e & 1) == 0);
#pragma unroll
    for (int i=0;i<4;i++){
        int r = ty*4 + i;
        int pr = pairs[r];
        if (pr < 0) continue;
#pragma unroll
        for (int j=0;j<4;j++){
            int c = n0 + tx*4 + j;
            float v = acc[i][j] + mb1[e*HMAX + c];
            v = use_gelu ? geluf(v) : fmaxf(v, 0.f);
            g_xmid[(size_t)pr*HMAX + c] = v;
        }
    }
}

// ---------------- MLP stage 2 ----------------
__global__ __launch_bounds__(256) void mlp2_gemm(
    const float* __restrict__ mw2, const float* __restrict__ mb2)
{
    int e = blockIdx.z;
    int hid = DM*(2 + (e>>2));
    int n0 = blockIdx.x*64;
    int cnt = g_cnt[NE+e];
    int m0 = blockIdx.y*64;
    if (m0 >= cnt) return;
    const int* list = g_list + (NE+e)*NPAIR;
    __shared__ int pairs[64];
    __shared__ float As[16][64];
    __shared__ float Ws[16][64];
    int tid = threadIdx.x;
    if (tid < 64) pairs[tid] = (m0+tid < cnt) ? list[m0+tid] : -1;
    __syncthreads();
    int tx = tid & 15, ty = tid >> 4;
    int lr = tid >> 2, lk = (tid & 3)*4;
    int wr = tid >> 4, wc = (tid & 15)*4;
    const float* Wg = mw2 + (size_t)e*HMAX*DM;
    float acc[4][4] = {};
    for (int k0=0;k0<hid;k0+=16){
        int pr = pairs[lr];
        float4 av = make_float4(0.f,0.f,0.f,0.f);
        if (pr >= 0) av = *(const float4*)&g_xmid[(size_t)pr*HMAX + k0 + lk];
        As[lk+0][lr]=av.x; As[lk+1][lr]=av.y; As[lk+2][lr]=av.z; As[lk+3][lr]=av.w;
        *(float4*)&Ws[wr][wc] = *(const float4*)&Wg[(size_t)(k0+wr)*DM + n0 + wc];
        __syncthreads();
#pragma unroll
        for (int kk=0;kk<16;kk++){
            float4 a4 = *(const float4*)&As[kk][ty*4];
            float4 b4 = *(const float4*)&Ws[kk][tx*4];
            float aa[4]={a4.x,a4.y,a4.z,a4.w};
            float bb[4]={b4.x,b4.y,b4.z,b4.w};
#pragma unroll
            for (int i=0;i<4;i++)
#pragma unroll
                for (int j=0;j<4;j++) acc[i][j] += aa[i]*bb[j];
        }
        __syncthreads();
    }
#pragma unroll
    for (int i=0;i<4;i++){
        int r = ty*4 + i;
        int pr = pairs[r];
        if (pr < 0) continue;
#pragma unroll
        for (int j=0;j<4;j++){
            int c = n0 + tx*4 + j;
            g_xmlp[(size_t)pr*DM + c] = acc[i][j] + mb2[e*DM + c];
        }
    }
}

// ---------------- post experts: gathered GEMM + optional LN + weighted scatter ----------------
__global__ __launch_bounds__(256) void post_expert(
    const float* __restrict__ qw, const float* __restrict__ qb,
    const float* __restrict__ qg, const float* __restrict__ qbb,
    float* __restrict__ out_y)
{
    int e = blockIdx.y;
    int cnt = g_cnt[2*NE+e];
    int m0 = blockIdx.x*64;
    if (m0 >= cnt) return;
    const int* list = g_list + (2*NE+e)*NPAIR;
    __shared__ int pairs[64];
    __shared__ float As[16][64];
    __shared__ float Ws[16][256];
    int tid = threadIdx.x;
    if (tid < 64) pairs[tid] = (m0+tid < cnt) ? list[m0+tid] : -1;
    __syncthreads();
    int tx = tid & 15, ry = tid >> 4;
    int lr = tid >> 2, lk = (tid & 3)*4;
    const float* Wg = qw + (size_t)e*DM*DM;
    float acc[4][16] = {};
    for (int k0=0;k0<DM;k0+=16){
        int pr = pairs[lr];
        float4 av = make_float4(0.f,0.f,0.f,0.f);
        if (pr >= 0) av = *(const float4*)&g_xmlp[(size_t)pr*DM + k0 + lk];
        As[lk+0][lr]=av.x; As[lk+1][lr]=av.y; As[lk+2][lr]=av.z; As[lk+3][lr]=av.w;
#pragma unroll
        for (int jj=0;jj<4;jj++){
            int idx = jj*1024 + tid*4;
            int kr = idx >> 8, c = idx & 255;
            *(float4*)&Ws[kr][c] = *(const float4*)&Wg[(size_t)(k0+kr)*DM + c];
        }
        __syncthreads();
#pragma unroll
        for (int kk=0;kk<16;kk++){
            float4 a4 = *(const float4*)&As[kk][ry*4];
            float aa[4]={a4.x,a4.y,a4.z,a4.w};
#pragma unroll
            for (int j4=0;j4<4;j4++){
                float4 b4 = *(const float4*)&Ws[kk][tx*16 + j4*4];
                float bb[4]={b4.x,b4.y,b4.z,b4.w};
#pragma unroll
                for (int i=0;i<4;i++)
#pragma unroll
                    for (int j=0;j<4;j++) acc[i][j4*4+j] += aa[i]*bb[j];
            }
        }
        __syncthreads();
    }
    bool do_ln = ((e & 1) == 0);
#pragma unroll
    for (int i=0;i<4;i++){
        int r = ry*4 + i;
        int pr = pairs[r];
        float y[16];
#pragma unroll
        for (int j=0;j<16;j++) y[j] = acc[i][j] + qb[e*DM + tx*16 + j];
        if (do_ln){
            float lsum = 0.f;
#pragma unroll
            for (int j=0;j<16;j++) lsum += y[j];
#pragma unroll
            for (int m=8;m>0;m>>=1) lsum += __shfl_xor_sync(0xffffffffu, lsum, m, 32);
            float mu = lsum * (1.0f/DM);
            float lss = 0.f;
#pragma unroll
            for (int j=0;j<16;j++){ float d=y[j]-mu; lss += d*d; }
#pragma unroll
            for (int m=8;m>0;m>>=1) lss += __shfl_xor_sync(0xffffffffu, lss, m, 32);
            float rstd = rsqrtf(lss*(1.0f/DM) + 1e-5f);
#pragma unroll
            for (int j=0;j<16;j++){
                int c = tx*16 + j;
                y[j] = (y[j]-mu)*rstd*qg[e*DM+c] + qbb[e*DM+c];
            }
        }
        if (pr >= 0){
            float w = g_topval[pr];
            int tok = pr >> 2;
#pragma unroll
            for (int j=0;j<16;j++){
                int c = tx*16 + j;
                atomicAdd(&out_y[(size_t)tok*DM + c], y[j]*w);
            }
        }
    }
}

// ---------------- host launch ----------------
extern "C" void kernel_launch(void* const* d_in, const int* in_sizes, int n_in,
                              void* d_out, int out_size)
{
    const float* x   = (const float*)d_in[0];
    const float* rw1 = (const float*)d_in[1];
    const float* rb1 = (const float*)d_in[2];
    const float* rw2 = (const float*)d_in[3];
    const float* rb2 = (const float*)d_in[4];
    const float* rw3 = (const float*)d_in[5];
    const float* rb3 = (const float*)d_in[6];
    const float* temp= (const float*)d_in[7];
    const float* pw  = (const float*)d_in[8];
    const float* pb  = (const float*)d_in[9];
    const float* pg  = (const float*)d_in[10];
    const float* pbb = (const float*)d_in[11];
    const float* mw1 = (const float*)d_in[12];
    const float* mb1 = (const float*)d_in[13];
    const float* mw2 = (const float*)d_in[14];
    const float* mb2 = (const float*)d_in[15];
    const float* qw  = (const float*)d_in[16];
    const float* qb  = (const float*)d_in[17];
    const float* qg  = (const float*)d_in[18];
    const float* qbb = (const float*)d_in[19];

    float* out      = (float*)d_out;
    float* out_y    = out;                     // [N_TOK*DM]
    float* out_loss = out + N_TOK*DM;          // [1]
    float* out_pw   = out + N_TOK*DM + 1;      // [N_TOK*PWY]

    void* p;
    cudaGetSymbolAddress(&p, g_h1);     float* h1 = (float*)p;
    cudaGetSymbolAddress(&p, g_h2);     float* h2 = (float*)p;
    cudaGetSymbolAddress(&p, g_scores); float* scores = (float*)p;
    cudaGetSymbolAddress(&p, g_freq);   float* freqp = (float*)p;
    cudaGetSymbolAddress(&p, g_cnt);    int*   cntp = (int*)p;

    cudaMemsetAsync(out_y, 0, (size_t)N_TOK*DM*sizeof(float), 0);
    cudaMemsetAsync(freqp, 0, PWY*sizeof(float), 0);
    cudaMemsetAsync(cntp,  0, 3*NE*sizeof(int), 0);

    // router
    gemm_plain<<<dim3(256/64, N_TOK/64), 256>>>(x,  rw1, rb1, h1,     N_TOK, 256,  256, 1);
    gemm_plain<<<dim3(128/64, N_TOK/64), 256>>>(h1, rw2, rb2, h2,     N_TOK, 128,  256, 1);
    gemm_plain<<<dim3(PWY/64, N_TOK/64), 256>>>(h2, rw3, rb3, scores, N_TOK, PWY,  128, 0);

    // softmax + topk + pathway weights (writes full rows, no memset needed)
    softmax_topk<<<N_TOK, 256>>>(temp, out_pw);

    // GLBL loss
    freq_partial<<<dim3(PWY/256, N_TOK/256), 256>>>();
    glbl_loss_kernel<<<1, 256>>>(out_loss);

    // routing
    build_lists<<<NPAIR/256, 256>>>();

    // experts
    pre_expert<<<dim3(NPAIR/64, NE), 256>>>(x, pw, pb, pg, pbb);
    mlp1_gemm<<<dim3(HMAX/64, NPAIR/64, NE), 256>>>(mw1, mb1);
    mlp2_gemm<<<dim3(DM/64, NPAIR/64, NE), 256>>>(mw2, mb2);
    post_expert<<<dim3(NPAIR/64, NE), 256>>>(qw, qb, qg, qbb, out_y);
}

// round 3
// speedup vs baseline: 1.4120x; 1.4066x over previous
#include <cuda_runtime.h>
#include <math.h>

#define N_TOK 2048
#define DM 256
#define PWY 4096
#define KSEL 4
#define NE 16
#define HMAX 1280
#define NPAIR (N_TOK*KSEL)

// ---------------- device scratch (static, no allocation) ----------------
__device__ float g_h1[N_TOK*256];
__device__ float g_h2[N_TOK*128];
__device__ float g_scores[N_TOK*PWY];     // raw scores, then overwritten with no-temp probs
__device__ float g_freq[PWY];
__device__ int   g_topidx[NPAIR];
__device__ float g_topval[NPAIR];
__device__ int   g_cnt[3*NE];
__device__ int   g_list[3*NE*NPAIR];
__device__ float g_xpre[NPAIR*DM];
__device__ float g_xmid[(size_t)NPAIR*HMAX];
__device__ float g_xmlp[NPAIR*DM];

__device__ __forceinline__ float geluf(float v){
    return 0.5f*v*(1.0f+erff(v*0.70710678118654752f));
}

// ---------------- small plain GEMM 64x64x16 (router layers 1,2) ----------------
__global__ __launch_bounds__(256) void gemm_plain(
    const float* __restrict__ A, const float* __restrict__ W,
    const float* __restrict__ bias, float* __restrict__ C,
    int M, int Nc, int Ka, int act)
{
    __shared__ float As[16][64];
    __shared__ float Ws[16][64];
    int tid = threadIdx.x;
    int m0 = blockIdx.y*64, n0 = blockIdx.x*64;
    int tx = tid & 15, ty = tid >> 4;
    int lr = tid >> 2, lk = (tid & 3)*4;
    int wr = tid >> 4, wc = (tid & 15)*4;
    float acc[4][4] = {};
    for (int k0 = 0; k0 < Ka; k0 += 16) {
        float4 av = *(const float4*)&A[(size_t)(m0+lr)*Ka + k0 + lk];
        As[lk+0][lr]=av.x; As[lk+1][lr]=av.y; As[lk+2][lr]=av.z; As[lk+3][lr]=av.w;
        *(float4*)&Ws[wr][wc] = *(const float4*)&W[(size_t)(k0+wr)*Nc + n0 + wc];
        __syncthreads();
#pragma unroll
        for (int kk = 0; kk < 16; kk++) {
            float4 a4 = *(const float4*)&As[kk][ty*4];
            float4 b4 = *(const float4*)&Ws[kk][tx*4];
            float aa[4]={a4.x,a4.y,a4.z,a4.w};
            float bb[4]={b4.x,b4.y,b4.z,b4.w};
#pragma unroll
            for (int i=0;i<4;i++)
#pragma unroll
                for (int j=0;j<4;j++) acc[i][j] += aa[i]*bb[j];
        }
        __syncthreads();
    }
#pragma unroll
    for (int i=0;i<4;i++){
        int r = m0 + ty*4 + i;
#pragma unroll
        for (int j=0;j<4;j++){
            int c = n0 + tx*4 + j;
            float v = acc[i][j] + bias[c];
            if (act==1) v = geluf(v);
            C[(size_t)r*Nc + c] = v;
        }
    }
}

// ---------------- big GEMM: 128x128x16, 8x8 micro, double-buffered ----------------
// listoff < 0: plain rows (m0+r). listoff >= 0: gathered rows from g_list.
__global__ __launch_bounds__(256,2) void gemm128_g(
    const float* __restrict__ A, int lda,
    const float* __restrict__ W, int ldw, long long wse,
    const float* __restrict__ bias, int bse,
    float* __restrict__ C, int ldc,
    int Kfix, int kvar, int nvar, int act, int listoff)
{
    int e = blockIdx.z;
    int hid = DM*(2 + (e>>2));
    int K = kvar ? hid : Kfix;
    int n0 = blockIdx.x*128;
    if (nvar && n0 >= hid) return;
    int m0 = blockIdx.y*128;
    const int* list = 0; int cnt = 0;
    if (listoff >= 0){
        cnt = g_cnt[listoff+e];
        if (m0 >= cnt) return;
        list = g_list + (size_t)(listoff+e)*NPAIR;
    }
    __shared__ int pairs[128];
    __shared__ float As[2][16][132];
    __shared__ float Ws[2][16][132];
    int tid = threadIdx.x;
    if (tid < 128)
        pairs[tid] = (listoff>=0) ? ((m0+tid < cnt) ? list[m0+tid] : -1) : (m0+tid);
    __syncthreads();

    int arow = tid>>1, ak = (tid&1)*8;
    int prA = pairs[arow];
    const float* Ab = (prA>=0) ? (A + (size_t)prA*lda) : 0;
    int wr = tid>>4, wc = (tid&15)*4;
    const float* Wg = W + (size_t)e*wse;
    int tx = tid&15, ty = tid>>4;

    float4 fa0, fa1, fw0, fw1;
    auto fetch = [&](int k0){
        if (Ab){ const float* ap = Ab + k0 + ak; fa0 = *(const float4*)ap; fa1 = *(const float4*)(ap+4); }
        else { fa0 = make_float4(0.f,0.f,0.f,0.f); fa1 = fa0; }
        const float* wp = Wg + (size_t)(k0+wr)*ldw + n0 + wc;
        fw0 = *(const float4*)wp; fw1 = *(const float4*)(wp+64);
    };
    auto stor = [&](int b){
        As[b][ak+0][arow]=fa0.x; As[b][ak+1][arow]=fa0.y; As[b][ak+2][arow]=fa0.z; As[b][ak+3][arow]=fa0.w;
        As[b][ak+4][arow]=fa1.x; As[b][ak+5][arow]=fa1.y; As[b][ak+6][arow]=fa1.z; As[b][ak+7][arow]=fa1.w;
        *(float4*)&Ws[b][wr][wc]    = fw0;
        *(float4*)&Ws[b][wr][wc+64] = fw1;
    };

    int nt = K/16;
    fetch(0); stor(0); __syncthreads();
    float acc[8][8] = {};
    for (int t=0; t<nt; t++){
        int b = t&1;
        if (t+1 < nt) fetch((t+1)*16);
#pragma unroll
        for (int kk=0; kk<16; kk++){
            float4 aA = *(const float4*)&As[b][kk][ty*4];
            float4 aB = *(const float4*)&As[b][kk][64+ty*4];
            float4 bA = *(const float4*)&Ws[b][kk][tx*4];
            float4 bB = *(const float4*)&Ws[b][kk][64+tx*4];
            float av[8]={aA.x,aA.y,aA.z,aA.w,aB.x,aB.y,aB.z,aB.w};
            float bv[8]={bA.x,bA.y,bA.z,bA.w,bB.x,bB.y,bB.z,bB.w};
#pragma unroll
            for (int i=0;i<8;i++)
#pragma unroll
                for (int j=0;j<8;j++) acc[i][j] += av[i]*bv[j];
        }
        if (t+1 < nt) stor((t+1)&1);
        __syncthreads();
    }

    float4 bias0 = *(const float4*)&bias[(size_t)e*bse + n0 + tx*4];
    float4 bias1 = *(const float4*)&bias[(size_t)e*bse + n0 + 64 + tx*4];
    bool relu_e = (act==2) || (act==3 && (e&1));
#pragma unroll
    for (int i=0;i<8;i++){
        int r = (i<4) ? (ty*4+i) : (64+ty*4+i-4);
        int pr = pairs[r];
        if (pr < 0) continue;
        float v0[4], v1[4];
        v0[0]=acc[i][0]+bias0.x; v0[1]=acc[i][1]+bias0.y; v0[2]=acc[i][2]+bias0.z; v0[3]=acc[i][3]+bias0.w;
        v1[0]=acc[i][4]+bias1.x; v1[1]=acc[i][5]+bias1.y; v1[2]=acc[i][6]+bias1.z; v1[3]=acc[i][7]+bias1.w;
        if (act){
            if (relu_e){
#pragma unroll
                for (int j=0;j<4;j++){ v0[j]=fmaxf(v0[j],0.f); v1[j]=fmaxf(v1[j],0.f); }
            } else {
#pragma unroll
                for (int j=0;j<4;j++){ v0[j]=geluf(v0[j]); v1[j]=geluf(v1[j]); }
            }
        }
        *(float4*)&C[(size_t)pr*ldc + n0 + tx*4]      = make_float4(v0[0],v0[1],v0[2],v0[3]);
        *(float4*)&C[(size_t)pr*ldc + n0 + 64 + tx*4] = make_float4(v1[0],v1[1],v1[2],v1[3]);
    }
}

// ---------------- softmax + topk + pathway_weights + probs writeback ----------------
__global__ __launch_bounds__(256) void softmax_topk(
    const float* __restrict__ temp, float* __restrict__ pwout)
{
    __shared__ float s[PWY];
    __shared__ float rv[256*4];
    __shared__ int   ri[256*4];
    __shared__ float red1[256];
    __shared__ float red2[256];
    __shared__ float pv[KSEL];
    int n = blockIdx.x, tid = threadIdx.x;
    float* srow = g_scores + (size_t)n*PWY;
    for (int i=0;i<4;i++){
        int idx = i*1024 + tid*4;
        *(float4*)&s[idx] = *(const float4*)&srow[idx];
    }
    __syncthreads();
    float invt = 1.0f/temp[0];

    // single pass: per-thread top4 + max
    float tv[4] = {-INFINITY,-INFINITY,-INFINITY,-INFINITY};
    int tix[4] = {PWY,PWY,PWY,PWY};
    float lm = -INFINITY;
#pragma unroll
    for (int i=0;i<16;i++){
        int j = tid + i*256;
        float v = s[j];
        lm = fmaxf(lm, v);
        if (v > tv[3] || (v == tv[3] && j < tix[3])){
            tv[3]=v; tix[3]=j;
#pragma unroll
            for (int q=3;q>0;q--){
                if (tv[q] > tv[q-1] || (tv[q]==tv[q-1] && tix[q] < tix[q-1])){
                    float tmv=tv[q]; tv[q]=tv[q-1]; tv[q-1]=tmv;
                    int tmi=tix[q]; tix[q]=tix[q-1]; tix[q-1]=tmi;
                }
            }
        }
    }
    red1[tid]=lm; __syncthreads();
    for (int off=128;off>0;off>>=1){ if(tid<off) red1[tid]=fmaxf(red1[tid],red1[tid+off]); __syncthreads(); }
    float m0 = red1[0]; __syncthreads();

    // both exp sums in one pass; cache no-temp exps
    float f[16]; float ls0=0.f, lst=0.f;
#pragma unroll
    for (int i=0;i<16;i++){
        int j = tid + i*256;
        float d = s[j]-m0;
        float e0 = __expf(d);
        f[i]=e0; ls0+=e0;
        lst += __expf(d*invt);
    }
    red1[tid]=ls0; red2[tid]=lst; __syncthreads();
    for (int off=128;off>0;off>>=1){
        if(tid<off){ red1[tid]+=red1[tid+off]; red2[tid]+=red2[tid+off]; }
        __syncthreads();
    }
    float inv0 = 1.0f/red1[0];
    float invsumt = 1.0f/red2[0];
    __syncthreads();

    // write no-temp probs back (freq kernel consumes them, no exp needed there)
#pragma unroll
    for (int i=0;i<16;i++) srow[tid + i*256] = f[i]*inv0;

    // merge top4 lists (log tree)
#pragma unroll
    for (int q=0;q<4;q++){ rv[tid*4+q]=tv[q]; ri[tid*4+q]=tix[q]; }
    __syncthreads();
    for (int off=128;off>0;off>>=1){
        if (tid < off){
            float a0[4], b0[4]; int ai[4], bi[4];
#pragma unroll
            for (int q=0;q<4;q++){
                a0[q]=rv[tid*4+q]; ai[q]=ri[tid*4+q];
                b0[q]=rv[(tid+off)*4+q]; bi[q]=ri[(tid+off)*4+q];
            }
            int ia=0, ib=0;
            float ov[4]; int oi[4];
#pragma unroll
            for (int q=0;q<4;q++){
                bool ta = (a0[ia] > b0[ib]) || (a0[ia]==b0[ib] && ai[ia] < bi[ib]);
                if (ta){ ov[q]=a0[ia]; oi[q]=ai[ia]; ia++; }
                else   { ov[q]=b0[ib]; oi[q]=bi[ib]; ib++; }
            }
#pragma unroll
            for (int q=0;q<4;q++){ rv[tid*4+q]=ov[q]; ri[tid*4+q]=oi[q]; }
        }
        __syncthreads();
    }

    if (tid < KSEL){
        int se = ri[tid];
        float p = __expf((s[se]-m0)*invt)*invsumt;
        pv[tid]=p;
        g_topidx[n*KSEL+tid]=se;
        g_topval[n*KSEL+tid]=p;
    }
    __syncthreads();
    float invps = 1.0f/(pv[0]+pv[1]+pv[2]+pv[3] + 1e-8f);
    int s0=ri[0], s1=ri[1], s2=ri[2], s3=ri[3];
    float w0=pv[0]*invps, w1=pv[1]*invps, w2=pv[2]*invps, w3=pv[3]*invps;
    float* prow = pwout + (size_t)n*PWY;
    for (int i=0;i<16;i++){
        int j = tid + i*256;
        float v = 0.f;
        if (j==s0) v=w0; else if (j==s1) v=w1; else if (j==s2) v=w2; else if (j==s3) v=w3;
        prow[j]=v;
    }
}

// ---------------- freq: pure column sums of probs ----------------
__global__ __launch_bounds__(256) void freq_partial()
{
    int p = blockIdx.x*256 + threadIdx.x;
    int nbeg = blockIdx.y*256;
    float acc = 0.f;
    for (int n=nbeg; n<nbeg+256; n++)
        acc += g_scores[(size_t)n*PWY + p];
    atomicAdd(&g_freq[p], acc);
}

__global__ __launch_bounds__(256) void glbl_loss_kernel(float* __restrict__ out)
{
    __shared__ float red[256];
    int tid = threadIdx.x;
    const float invN = 1.0f/(float)N_TOK;
    float lsum = 0.f;
    for (int i=0;i<PWY/256;i++) lsum += g_freq[tid+i*256]*invN;
    red[tid]=lsum; __syncthreads();
    for (int off=128;off>0;off>>=1){ if(tid<off) red[tid]+=red[tid+off]; __syncthreads(); }
    float mean = red[0]/(float)PWY; __syncthreads();
    float lss = 0.f;
    for (int i=0;i<PWY/256;i++){
        float d = g_freq[tid+i*256]*invN - mean;
        lss += d*d;
    }
    red[tid]=lss; __syncthreads();
    for (int off=128;off>0;off>>=1){ if(tid<off) red[tid]+=red[tid+off]; __syncthreads(); }
    if (tid==0) out[0] = (float)PWY * (red[0]/(float)(PWY-1));
}

// ---------------- routing lists ----------------
__global__ __launch_bounds__(256) void build_lists()
{
    int i = blockIdx.x*256 + threadIdx.x;
    if (i >= NPAIR) return;
    int idx = g_topidx[i];
    int pe = idx >> 8, rem = idx & 255;
    int me = rem >> 4, qe = rem & 15;
    int pos;
    pos = atomicAdd(&g_cnt[pe], 1);         g_list[pe*NPAIR + pos] = i;
    pos = atomicAdd(&g_cnt[NE+me], 1);      g_list[(NE+me)*NPAIR + pos] = i;
    pos = atomicAdd(&g_cnt[2*NE+qe], 1);    g_list[(2*NE+qe)*NPAIR + pos] = i;
}

// ---------------- pre experts: 64x256 gathered GEMM + LN + act, double-buffered ----------------
__global__ __launch_bounds__(256) void pre_expert(
    const float* __restrict__ x, const float* __restrict__ pwgt,
    const float* __restrict__ pb, const float* __restrict__ pg,
    const float* __restrict__ pbb)
{
    int e = blockIdx.y;
    int cnt = g_cnt[e];
    int m0 = blockIdx.x*64;
    if (m0 >= cnt) return;
    __shared__ int pairs[64];
    __shared__ float As[2][16][68];
    __shared__ float Ws[2][16][256];
    int tid = threadIdx.x;
    if (tid < 64) pairs[tid] = (m0+tid < cnt) ? g_list[e*NPAIR + m0+tid] : -1;
    __syncthreads();
    int arow = tid>>2, ak = (tid&3)*4;
    int prA = pairs[arow];
    const float* Arow = (prA>=0) ? (x + (size_t)(prA>>2)*DM) : 0;
    const float* Wg = pwgt + (size_t)e*DM*DM;
    int tx = tid&15, ry = tid>>4;

    float4 fa, fw[4];
    auto fetch = [&](int k0){
        fa = Arow ? *(const float4*)(Arow + k0 + ak) : make_float4(0.f,0.f,0.f,0.f);
#pragma unroll
        for (int jj=0;jj<4;jj++){
            int idx = jj*1024 + tid*4;
            fw[jj] = *(const float4*)&Wg[(size_t)(k0+(idx>>8))*DM + (idx&255)];
        }
    };
    auto stor = [&](int b){
        As[b][ak+0][arow]=fa.x; As[b][ak+1][arow]=fa.y; As[b][ak+2][arow]=fa.z; As[b][ak+3][arow]=fa.w;
#pragma unroll
        for (int jj=0;jj<4;jj++){
            int idx = jj*1024 + tid*4;
            *(float4*)&Ws[b][idx>>8][idx&255] = fw[jj];
        }
    };
    fetch(0); stor(0); __syncthreads();
    float acc[4][16] = {};
    for (int t=0;t<16;t++){
        int b = t&1;
        if (t<15) fetch((t+1)*16);
#pragma unroll
        for (int kk=0;kk<16;kk++){
            float4 a4 = *(const float4*)&As[b][kk][ry*4];
            float av[4]={a4.x,a4.y,a4.z,a4.w};
#pragma unroll
            for (int j4=0;j4<4;j4++){
                float4 b4 = *(const float4*)&Ws[b][kk][j4*64 + tx*4];
                float bv[4]={b4.x,b4.y,b4.z,b4.w};
#pragma unroll
                for (int i=0;i<4;i++)
#pragma unroll
                    for (int j=0;j<4;j++) acc[i][j4*4+j] += av[i]*bv[j];
            }
        }
        if (t<15) stor((t+1)&1);
        __syncthreads();
    }
    int actm = e % 3;
#pragma unroll
    for (int i=0;i<4;i++){
        int r = ry*4 + i;
        int pr = pairs[r];
        float y[16]; float lsum = 0.f;
#pragma unroll
        for (int j=0;j<16;j++){
            int c = (j>>2)*64 + tx*4 + (j&3);
            y[j] = acc[i][j] + pb[e*DM + c];
            lsum += y[j];
        }
#pragma unroll
        for (int m=8;m>0;m>>=1) lsum += __shfl_xor_sync(0xffffffffu, lsum, m, 32);
        float mu = lsum * (1.0f/DM);
        float lss = 0.f;
#pragma unroll
        for (int j=0;j<16;j++){ float d=y[j]-mu; lss += d*d; }
#pragma unroll
        for (int m=8;m>0;m>>=1) lss += __shfl_xor_sync(0xffffffffu, lss, m, 32);
        float rstd = rsqrtf(lss*(1.0f/DM) + 1e-5f);
        if (pr >= 0){
            float* orow = g_xpre + (size_t)pr*DM;
#pragma unroll
            for (int j4=0;j4<4;j4++){
                float o[4];
#pragma unroll
                for (int jc=0;jc<4;jc++){
                    int c = j4*64 + tx*4 + jc;
                    float v = (y[j4*4+jc]-mu)*rstd*pg[e*DM+c] + pbb[e*DM+c];
                    o[jc] = (actm==0) ? geluf(v) : (actm==1) ? fmaxf(v,0.f) : tanhf(v);
                }
                *(float4*)&orow[j4*64 + tx*4] = make_float4(o[0],o[1],o[2],o[3]);
            }
        }
    }
}

// ---------------- post experts: 64x256 gathered GEMM + optional LN + weighted scatter ----------------
__global__ __launch_bounds__(256) void post_expert(
    const float* __restrict__ qw, const float* __restrict__ qb,
    const float* __restrict__ qg, const float* __restrict__ qbb,
    float* __restrict__ out_y)
{
    int e = blockIdx.y;
    int cnt = g_cnt[2*NE+e];
    int m0 = blockIdx.x*64;
    if (m0 >= cnt) return;
    __shared__ int pairs[64];
    __shared__ float As[2][16][68];
    __shared__ float Ws[2][16][256];
    int tid = threadIdx.x;
    if (tid < 64) pairs[tid] = (m0+tid < cnt) ? g_list[(2*NE+e)*NPAIR + m0+tid] : -1;
    __syncthreads();
    int arow = tid>>2, ak = (tid&3)*4;
    int prA = pairs[arow];
    const float* Arow = (prA>=0) ? (g_xmlp + (size_t)prA*DM) : 0;
    const float* Wg = qw + (size_t)e*DM*DM;
    int tx = tid&15, ry = tid>>4;

    float4 fa, fw[4];
    auto fetch = [&](int k0){
        fa = Arow ? *(const float4*)(Arow + k0 + ak) : make_float4(0.f,0.f,0.f,0.f);
#pragma unroll
        for (int jj=0;jj<4;jj++){
            int idx = jj*1024 + tid*4;
            fw[jj] = *(const float4*)&Wg[(size_t)(k0+(idx>>8))*DM + (idx&255)];
        }
    };
    auto stor = [&](int b){
        As[b][ak+0][arow]=fa.x; As[b][ak+1][arow]=fa.y; As[b][ak+2][arow]=fa.z; As[b][ak+3][arow]=fa.w;
#pragma unroll
        for (int jj=0;jj<4;jj++){
            int idx = jj*1024 + tid*4;
            *(float4*)&Ws[b][idx>>8][idx&255] = fw[jj];
        }
    };
    fetch(0); stor(0); __syncthreads();
    float acc[4][16] = {};
    for (int t=0;t<16;t++){
        int b = t&1;
        if (t<15) fetch((t+1)*16);
#pragma unroll
        for (int kk=0;kk<16;kk++){
            float4 a4 = *(const float4*)&As[b][kk][ry*4];
            float av[4]={a4.x,a4.y,a4.z,a4.w};
#pragma unroll
            for (int j4=0;j4<4;j4++){
                float4 b4 = *(const float4*)&Ws[b][kk][j4*64 + tx*4];
                float bv[4]={b4.x,b4.y,b4.z,b4.w};
#pragma unroll
                for (int i=0;i<4;i++)
#pragma unroll
                    for (int j=0;j<4;j++) acc[i][j4*4+j] += av[i]*bv[j];
            }
        }
        if (t<15) stor((t+1)&1);
        __syncthreads();
    }
    bool do_ln = ((e & 1) == 0);
#pragma unroll
    for (int i=0;i<4;i++){
        int r = ry*4 + i;
        int pr = pairs[r];
        float y[16];
#pragma unroll
        for (int j=0;j<16;j++){
            int c = (j>>2)*64 + tx*4 + (j&3);
            y[j] = acc[i][j] + qb[e*DM + c];
        }
        if (do_ln){
            float lsum = 0.f;
#pragma unroll
            for (int j=0;j<16;j++) lsum += y[j];
#pragma unroll
            for (int m=8;m>0;m>>=1) lsum += __shfl_xor_sync(0xffffffffu, lsum, m, 32);
            float mu = lsum * (1.0f/DM);
            float lss = 0.f;
#pragma unroll
            for (int j=0;j<16;j++){ float d=y[j]-mu; lss += d*d; }
#pragma unroll
            for (int m=8;m>0;m>>=1) lss += __shfl_xor_sync(0xffffffffu, lss, m, 32);
            float rstd = rsqrtf(lss*(1.0f/DM) + 1e-5f);
#pragma unroll
            for (int j=0;j<16;j++){
                int c = (j>>2)*64 + tx*4 + (j&3);
                y[j] = (y[j]-mu)*rstd*qg[e*DM+c] + qbb[e*DM+c];
            }
        }
        if (pr >= 0){
            float w = g_topval[pr];
            int tok = pr >> 2;
#pragma unroll
            for (int j=0;j<16;j++){
                int c = (j>>2)*64 + tx*4 + (j&3);
                atomicAdd(&out_y[(size_t)tok*DM + c], y[j]*w);
            }
        }
    }
}

// ---------------- host launch ----------------
extern "C" void kernel_launch(void* const* d_in, const int* in_sizes, int n_in,
                              void* d_out, int out_size)
{
    const float* x   = (const float*)d_in[0];
    const float* rw1 = (const float*)d_in[1];
    const float* rb1 = (const float*)d_in[2];
    const float* rw2 = (const float*)d_in[3];
    const float* rb2 = (const float*)d_in[4];
    const float* rw3 = (const float*)d_in[5];
    const float* rb3 = (const float*)d_in[6];
    const float* temp= (const float*)d_in[7];
    const float* pw  = (const float*)d_in[8];
    const float* pb  = (const float*)d_in[9];
    const float* pg  = (const float*)d_in[10];
    const float* pbb = (const float*)d_in[11];
    const float* mw1 = (const float*)d_in[12];
    const float* mb1 = (const float*)d_in[13];
    const float* mw2 = (const float*)d_in[14];
    const float* mb2 = (const float*)d_in[15];
    const float* qw  = (const float*)d_in[16];
    const float* qb  = (const float*)d_in[17];
    const float* qg  = (const float*)d_in[18];
    const float* qbb = (const float*)d_in[19];

    float* out      = (float*)d_out;
    float* out_y    = out;                     // [N_TOK*DM]
    float* out_loss = out + N_TOK*DM;          // [1]
    float* out_pw   = out + N_TOK*DM + 1;      // [N_TOK*PWY]

    void* p;
    cudaGetSymbolAddress(&p, g_h1);     float* h1 = (float*)p;
    cudaGetSymbolAddress(&p, g_h2);     float* h2 = (float*)p;
    cudaGetSymbolAddress(&p, g_scores); float* scores = (float*)p;
    cudaGetSymbolAddress(&p, g_freq);   float* freqp = (float*)p;
    cudaGetSymbolAddress(&p, g_cnt);    int*   cntp = (int*)p;
    cudaGetSymbolAddress(&p, g_xpre);   float* xpre = (float*)p;
    cudaGetSymbolAddress(&p, g_xmid);   float* xmid = (float*)p;
    cudaGetSymbolAddress(&p, g_xmlp);   float* xmlp = (float*)p;

    cudaMemsetAsync(out_y, 0, (size_t)N_TOK*DM*sizeof(float), 0);
    cudaMemsetAsync(freqp, 0, PWY*sizeof(float), 0);
    cudaMemsetAsync(cntp,  0, 3*NE*sizeof(int), 0);

    // router layers 1,2 (small)
    gemm_plain<<<dim3(256/64, N_TOK/64), 256>>>(x,  rw1, rb1, h1, N_TOK, 256, 256, 1);
    gemm_plain<<<dim3(128/64, N_TOK/64), 256>>>(h1, rw2, rb2, h2, N_TOK, 128, 256, 1);
    // router layer 3 (big): scores = h2 @ rw3 + rb3
    gemm128_g<<<dim3(PWY/128, N_TOK/128, 1), 256>>>(
        h2, 128, rw3, PWY, 0LL, rb3, 0, scores, PWY, 128, 0, 0, 0, -1);

    // softmax + topk + pathway weights + probs writeback
    softmax_topk<<<N_TOK, 256>>>(temp, out_pw);

    // GLBL loss (probs column sums)
    freq_partial<<<dim3(PWY/256, N_TOK/256), 256>>>();
    glbl_loss_kernel<<<1, 256>>>(out_loss);

    // routing
    build_lists<<<NPAIR/256, 256>>>();

    // experts
    pre_expert<<<dim3(NPAIR/64, NE), 256>>>(x, pw, pb, pg, pbb);
    gemm128_g<<<dim3(HMAX/128, NPAIR/128, NE), 256>>>(
        xpre, DM, mw1, HMAX, (long long)DM*HMAX, mb1, HMAX, xmid, HMAX,
        DM, 0, 1, 3, NE);
    gemm128_g<<<dim3(DM/128, NPAIR/128, NE), 256>>>(
        xmid, HMAX, mw2, DM, (long long)HMAX*DM, mb2, DM, xmlp, DM,
        0, 1, 0, 0, NE);
    post_expert<<<dim3(NPAIR/64, NE), 256>>>(qw, qb, qg, qbb, out_y);
}

// round 4
// speedup vs baseline: 1.4886x; 1.0542x over previous
#include <cuda_runtime.h>
#include <math.h>

#define N_TOK 2048
#define DM 256
#define PWY 4096
#define KSEL 4
#define NE 16
#define HMAX 1280
#define NPAIR (N_TOK*KSEL)

// packed f32x2 helpers (Blackwell dual fp32 pipe; bit-exact vs scalar FFMA)
#define PACK2(out, lo, hi)   asm("mov.b64 %0, {%1, %2};" : "=l"(out) : "f"(lo), "f"(hi))
#define UNPACK2(lo, hi, in)  asm("mov.b64 {%0, %1}, %2;" : "=f"(lo), "=f"(hi) : "l"(in))
#define FMA2(d, a, b, c)     asm("fma.rn.f32x2 %0, %1, %2, %3;" : "=l"(d) : "l"(a), "l"(b), "l"(c))
typedef unsigned long long u64;

// ---------------- device scratch (static, no allocation) ----------------
__device__ float g_h1[N_TOK*256];
__device__ float g_h2[N_TOK*128];
__device__ float g_scores[N_TOK*PWY];     // raw scores, then overwritten with no-temp probs
__device__ float g_freq[PWY];
__device__ int   g_topidx[NPAIR];
__device__ float g_topval[NPAIR];
__device__ int   g_cnt[3*NE];
__device__ int   g_list[3*NE*NPAIR];
__device__ float g_xpre[NPAIR*DM];
__device__ float g_xmid[(size_t)NPAIR*HMAX];
__device__ float g_xmlp[NPAIR*DM];

__device__ __forceinline__ float geluf(float v){
    return 0.5f*v*(1.0f+erff(v*0.70710678118654752f));
}

// ---------------- small plain GEMM 64x64x16 (router layers 1,2) ----------------
__global__ __launch_bounds__(256) void gemm_plain(
    const float* __restrict__ A, const float* __restrict__ W,
    const float* __restrict__ bias, float* __restrict__ C,
    int M, int Nc, int Ka, int act)
{
    __shared__ float As[16][64];
    __shared__ float Ws[16][64];
    int tid = threadIdx.x;
    int m0 = blockIdx.y*64, n0 = blockIdx.x*64;
    int tx = tid & 15, ty = tid >> 4;
    int lr = tid >> 2, lk = (tid & 3)*4;
    int wr = tid >> 4, wc = (tid & 15)*4;
    u64 acc2[4][2] = {};
    for (int k0 = 0; k0 < Ka; k0 += 16) {
        float4 av = *(const float4*)&A[(size_t)(m0+lr)*Ka + k0 + lk];
        As[lk+0][lr]=av.x; As[lk+1][lr]=av.y; As[lk+2][lr]=av.z; As[lk+3][lr]=av.w;
        *(float4*)&Ws[wr][wc] = *(const float4*)&W[(size_t)(k0+wr)*Nc + n0 + wc];
        __syncthreads();
#pragma unroll
        for (int kk = 0; kk < 16; kk++) {
            float4 a4 = *(const float4*)&As[kk][ty*4];
            float4 b4 = *(const float4*)&Ws[kk][tx*4];
            u64 bp[2];
            PACK2(bp[0], b4.x, b4.y); PACK2(bp[1], b4.z, b4.w);
            float aa[4]={a4.x,a4.y,a4.z,a4.w};
#pragma unroll
            for (int i=0;i<4;i++){
                u64 ap; PACK2(ap, aa[i], aa[i]);
                FMA2(acc2[i][0], ap, bp[0], acc2[i][0]);
                FMA2(acc2[i][1], ap, bp[1], acc2[i][1]);
            }
        }
        __syncthreads();
    }
#pragma unroll
    for (int i=0;i<4;i++){
        int r = m0 + ty*4 + i;
        float a0,a1,a2,a3;
        UNPACK2(a0,a1,acc2[i][0]); UNPACK2(a2,a3,acc2[i][1]);
        float acc[4]={a0,a1,a2,a3};
#pragma unroll
        for (int j=0;j<4;j++){
            int c = n0 + tx*4 + j;
            float v = acc[j] + bias[c];
            if (act==1) v = geluf(v);
            C[(size_t)r*Nc + c] = v;
        }
    }
}

// ---------------- big GEMM: 128x128x16, 8x8 micro, double-buffered, f32x2 ----------------
// listoff < 0: plain rows (m0+r). listoff >= 0: gathered rows from g_list.
__global__ __launch_bounds__(256,2) void gemm128_g(
    const float* __restrict__ A, int lda,
    const float* __restrict__ W, int ldw, long long wse,
    const float* __restrict__ bias, int bse,
    float* __restrict__ C, int ldc,
    int Kfix, int kvar, int nvar, int act, int listoff)
{
    int e = blockIdx.z;
    int hid = DM*(2 + (e>>2));
    int K = kvar ? hid : Kfix;
    int n0 = blockIdx.x*128;
    if (nvar && n0 >= hid) return;
    int m0 = blockIdx.y*128;
    const int* list = 0; int cnt = 0;
    if (listoff >= 0){
        cnt = g_cnt[listoff+e];
        if (m0 >= cnt) return;
        list = g_list + (size_t)(listoff+e)*NPAIR;
    }
    __shared__ int pairs[128];
    __shared__ float As[2][16][132];
    __shared__ float Ws[2][16][132];
    int tid = threadIdx.x;
    if (tid < 128)
        pairs[tid] = (listoff>=0) ? ((m0+tid < cnt) ? list[m0+tid] : -1) : (m0+tid);
    __syncthreads();

    int arow = tid>>1, ak = (tid&1)*8;
    int prA = pairs[arow];
    const float* Ab = (prA>=0) ? (A + (size_t)prA*lda) : 0;
    int wr = tid>>4, wc = (tid&15)*4;
    const float* Wg = W + (size_t)e*wse;
    int tx = tid&15, ty = tid>>4;

    float4 fa0, fa1, fw0, fw1;
    auto fetch = [&](int k0){
        if (Ab){ const float* ap = Ab + k0 + ak; fa0 = *(const float4*)ap; fa1 = *(const float4*)(ap+4); }
        else { fa0 = make_float4(0.f,0.f,0.f,0.f); fa1 = fa0; }
        const float* wp = Wg + (size_t)(k0+wr)*ldw + n0 + wc;
        fw0 = *(const float4*)wp; fw1 = *(const float4*)(wp+64);
    };
    auto stor = [&](int b){
        As[b][ak+0][arow]=fa0.x; As[b][ak+1][arow]=fa0.y; As[b][ak+2][arow]=fa0.z; As[b][ak+3][arow]=fa0.w;
        As[b][ak+4][arow]=fa1.x; As[b][ak+5][arow]=fa1.y; As[b][ak+6][arow]=fa1.z; As[b][ak+7][arow]=fa1.w;
        *(float4*)&Ws[b][wr][wc]    = fw0;
        *(float4*)&Ws[b][wr][wc+64] = fw1;
    };

    int nt = K/16;
    fetch(0); stor(0); __syncthreads();
    u64 acc2[8][4] = {};
    for (int t=0; t<nt; t++){
        int b = t&1;
        if (t+1 < nt) fetch((t+1)*16);
#pragma unroll
        for (int kk=0; kk<16; kk++){
            float4 aA = *(const float4*)&As[b][kk][ty*4];
            float4 aB = *(const float4*)&As[b][kk][64+ty*4];
            float4 bA = *(const float4*)&Ws[b][kk][tx*4];
            float4 bB = *(const float4*)&Ws[b][kk][64+tx*4];
            u64 bp[4];
            PACK2(bp[0], bA.x, bA.y); PACK2(bp[1], bA.z, bA.w);
            PACK2(bp[2], bB.x, bB.y); PACK2(bp[3], bB.z, bB.w);
            float av[8]={aA.x,aA.y,aA.z,aA.w,aB.x,aB.y,aB.z,aB.w};
#pragma unroll
            for (int i=0;i<8;i++){
                u64 ap; PACK2(ap, av[i], av[i]);
#pragma unroll
                for (int j=0;j<4;j++) FMA2(acc2[i][j], ap, bp[j], acc2[i][j]);
            }
        }
        if (t+1 < nt) stor((t+1)&1);
        __syncthreads();
    }

    float4 bias0 = *(const float4*)&bias[(size_t)e*bse + n0 + tx*4];
    float4 bias1 = *(const float4*)&bias[(size_t)e*bse + n0 + 64 + tx*4];
    bool relu_e = (act==2) || (act==3 && (e&1));
#pragma unroll
    for (int i=0;i<8;i++){
        int r = (i<4) ? (ty*4+i) : (64+ty*4+i-4);
        int pr = pairs[r];
        if (pr < 0) continue;
        float acc[8];
        UNPACK2(acc[0],acc[1],acc2[i][0]); UNPACK2(acc[2],acc[3],acc2[i][1]);
        UNPACK2(acc[4],acc[5],acc2[i][2]); UNPACK2(acc[6],acc[7],acc2[i][3]);
        float v0[4], v1[4];
        v0[0]=acc[0]+bias0.x; v0[1]=acc[1]+bias0.y; v0[2]=acc[2]+bias0.z; v0[3]=acc[3]+bias0.w;
        v1[0]=acc[4]+bias1.x; v1[1]=acc[5]+bias1.y; v1[2]=acc[6]+bias1.z; v1[3]=acc[7]+bias1.w;
        if (act){
            if (relu_e){
#pragma unroll
                for (int j=0;j<4;j++){ v0[j]=fmaxf(v0[j],0.f); v1[j]=fmaxf(v1[j],0.f); }
            } else {
#pragma unroll
                for (int j=0;j<4;j++){ v0[j]=geluf(v0[j]); v1[j]=geluf(v1[j]); }
            }
        }
        *(float4*)&C[(size_t)pr*ldc + n0 + tx*4]      = make_float4(v0[0],v0[1],v0[2],v0[3]);
        *(float4*)&C[(size_t)pr*ldc + n0 + 64 + tx*4] = make_float4(v1[0],v1[1],v1[2],v1[3]);
    }
}

// ---------------- softmax + topk + pathway_weights + probs writeback ----------------
__global__ __launch_bounds__(256) void softmax_topk(
    const float* __restrict__ temp, float* __restrict__ pwout)
{
    __shared__ float s[PWY];
    __shared__ float rv[256*4];
    __shared__ int   ri[256*4];
    __shared__ float red1[256];
    __shared__ float red2[256];
    __shared__ float pv[KSEL];
    int n = blockIdx.x, tid = threadIdx.x;
    float* srow = g_scores + (size_t)n*PWY;
    for (int i=0;i<4;i++){
        int idx = i*1024 + tid*4;
        *(float4*)&s[idx] = *(const float4*)&srow[idx];
    }
    __syncthreads();
    float invt = 1.0f/temp[0];

    // single pass: per-thread top4 + max
    float tv[4] = {-INFINITY,-INFINITY,-INFINITY,-INFINITY};
    int tix[4] = {PWY,PWY,PWY,PWY};
    float lm = -INFINITY;
#pragma unroll
    for (int i=0;i<16;i++){
        int j = tid + i*256;
        float v = s[j];
        lm = fmaxf(lm, v);
        if (v > tv[3] || (v == tv[3] && j < tix[3])){
            tv[3]=v; tix[3]=j;
#pragma unroll
            for (int q=3;q>0;q--){
                if (tv[q] > tv[q-1] || (tv[q]==tv[q-1] && tix[q] < tix[q-1])){
                    float tmv=tv[q]; tv[q]=tv[q-1]; tv[q-1]=tmv;
                    int tmi=tix[q]; tix[q]=tix[q-1]; tix[q-1]=tmi;
                }
            }
        }
    }
    red1[tid]=lm; __syncthreads();
    for (int off=128;off>0;off>>=1){ if(tid<off) red1[tid]=fmaxf(red1[tid],red1[tid+off]); __syncthreads(); }
    float m0 = red1[0]; __syncthreads();

    // both exp sums in one pass; cache no-temp exps
    float f[16]; float ls0=0.f, lst=0.f;
#pragma unroll
    for (int i=0;i<16;i++){
        int j = tid + i*256;
        float d = s[j]-m0;
        float e0 = __expf(d);
        f[i]=e0; ls0+=e0;
        lst += __expf(d*invt);
    }
    red1[tid]=ls0; red2[tid]=lst; __syncthreads();
    for (int off=128;off>0;off>>=1){
        if(tid<off){ red1[tid]+=red1[tid+off]; red2[tid]+=red2[tid+off]; }
        __syncthreads();
    }
    float inv0 = 1.0f/red1[0];
    float invsumt = 1.0f/red2[0];
    __syncthreads();

    // write no-temp probs back (freq kernel consumes them, no exp needed there)
#pragma unroll
    for (int i=0;i<16;i++) srow[tid + i*256] = f[i]*inv0;

    // merge top4 lists (log tree)
#pragma unroll
    for (int q=0;q<4;q++){ rv[tid*4+q]=tv[q]; ri[tid*4+q]=tix[q]; }
    __syncthreads();
    for (int off=128;off>0;off>>=1){
        if (tid < off){
            float a0[4], b0[4]; int ai[4], bi[4];
#pragma unroll
            for (int q=0;q<4;q++){
                a0[q]=rv[tid*4+q]; ai[q]=ri[tid*4+q];
                b0[q]=rv[(tid+off)*4+q]; bi[q]=ri[(tid+off)*4+q];
            }
            int ia=0, ib=0;
            float ov[4]; int oi[4];
#pragma unroll
            for (int q=0;q<4;q++){
                bool ta = (a0[ia] > b0[ib]) || (a0[ia]==b0[ib] && ai[ia] < bi[ib]);
                if (ta){ ov[q]=a0[ia]; oi[q]=ai[ia]; ia++; }
                else   { ov[q]=b0[ib]; oi[q]=bi[ib]; ib++; }
            }
#pragma unroll
            for (int q=0;q<4;q++){ rv[tid*4+q]=ov[q]; ri[tid*4+q]=oi[q]; }
        }
        __syncthreads();
    }

    if (tid < KSEL){
        int se = ri[tid];
        float p = __expf((s[se]-m0)*invt)*invsumt;
        pv[tid]=p;
        g_topidx[n*KSEL+tid]=se;
        g_topval[n*KSEL+tid]=p;
    }
    __syncthreads();
    float invps = 1.0f/(pv[0]+pv[1]+pv[2]+pv[3] + 1e-8f);
    int s0=ri[0], s1=ri[1], s2=ri[2], s3=ri[3];
    float w0=pv[0]*invps, w1=pv[1]*invps, w2=pv[2]*invps, w3=pv[3]*invps;
    float* prow = pwout + (size_t)n*PWY;
    for (int i=0;i<16;i++){
        int j = tid + i*256;
        float v = 0.f;
        if (j==s0) v=w0; else if (j==s1) v=w1; else if (j==s2) v=w2; else if (j==s3) v=w3;
        prow[j]=v;
    }
}

// ---------------- freq: pure column sums of probs ----------------
__global__ __launch_bounds__(256) void freq_partial()
{
    int p = blockIdx.x*256 + threadIdx.x;
    int nbeg = blockIdx.y*256;
    float acc = 0.f;
    for (int n=nbeg; n<nbeg+256; n++)
        acc += g_scores[(size_t)n*PWY + p];
    atomicAdd(&g_freq[p], acc);
}

__global__ __launch_bounds__(256) void glbl_loss_kernel(float* __restrict__ out)
{
    __shared__ float red[256];
    int tid = threadIdx.x;
    const float invN = 1.0f/(float)N_TOK;
    float lsum = 0.f;
    for (int i=0;i<PWY/256;i++) lsum += g_freq[tid+i*256]*invN;
    red[tid]=lsum; __syncthreads();
    for (int off=128;off>0;off>>=1){ if(tid<off) red[tid]+=red[tid+off]; __syncthreads(); }
    float mean = red[0]/(float)PWY; __syncthreads();
    float lss = 0.f;
    for (int i=0;i<PWY/256;i++){
        float d = g_freq[tid+i*256]*invN - mean;
        lss += d*d;
    }
    red[tid]=lss; __syncthreads();
    for (int off=128;off>0;off>>=1){ if(tid<off) red[tid]+=red[tid+off]; __syncthreads(); }
    if (tid==0) out[0] = (float)PWY * (red[0]/(float)(PWY-1));
}

// ---------------- routing lists ----------------
__global__ __launch_bounds__(256) void build_lists()
{
    int i = blockIdx.x*256 + threadIdx.x;
    if (i >= NPAIR) return;
    int idx = g_topidx[i];
    int pe = idx >> 8, rem = idx & 255;
    int me = rem >> 4, qe = rem & 15;
    int pos;
    pos = atomicAdd(&g_cnt[pe], 1);         g_list[pe*NPAIR + pos] = i;
    pos = atomicAdd(&g_cnt[NE+me], 1);      g_list[(NE+me)*NPAIR + pos] = i;
    pos = atomicAdd(&g_cnt[2*NE+qe], 1);    g_list[(2*NE+qe)*NPAIR + pos] = i;
}

// ---------------- pre experts: 64x256 gathered GEMM + LN + act, f32x2 ----------------
__global__ __launch_bounds__(256) void pre_expert(
    const float* __restrict__ x, const float* __restrict__ pwgt,
    const float* __restrict__ pb, const float* __restrict__ pg,
    const float* __restrict__ pbb)
{
    int e = blockIdx.y;
    int cnt = g_cnt[e];
    int m0 = blockIdx.x*64;
    if (m0 >= cnt) return;
    __shared__ int pairs[64];
    __shared__ float As[2][16][68];
    __shared__ float Ws[2][16][256];
    int tid = threadIdx.x;
    if (tid < 64) pairs[tid] = (m0+tid < cnt) ? g_list[e*NPAIR + m0+tid] : -1;
    __syncthreads();
    int arow = tid>>2, ak = (tid&3)*4;
    int prA = pairs[arow];
    const float* Arow = (prA>=0) ? (x + (size_t)(prA>>2)*DM) : 0;
    const float* Wg = pwgt + (size_t)e*DM*DM;
    int tx = tid&15, ry = tid>>4;

    float4 fa, fw[4];
    auto fetch = [&](int k0){
        fa = Arow ? *(const float4*)(Arow + k0 + ak) : make_float4(0.f,0.f,0.f,0.f);
#pragma unroll
        for (int jj=0;jj<4;jj++){
            int idx = jj*1024 + tid*4;
            fw[jj] = *(const float4*)&Wg[(size_t)(k0+(idx>>8))*DM + (idx&255)];
        }
    };
    auto stor = [&](int b){
        As[b][ak+0][arow]=fa.x; As[b][ak+1][arow]=fa.y; As[b][ak+2][arow]=fa.z; As[b][ak+3][arow]=fa.w;
#pragma unroll
        for (int jj=0;jj<4;jj++){
            int idx = jj*1024 + tid*4;
            *(float4*)&Ws[b][idx>>8][idx&255] = fw[jj];
        }
    };
    fetch(0); stor(0); __syncthreads();
    u64 acc2[4][8] = {};
    for (int t=0;t<16;t++){
        int b = t&1;
        if (t<15) fetch((t+1)*16);
#pragma unroll
        for (int kk=0;kk<16;kk++){
            float4 a4 = *(const float4*)&As[b][kk][ry*4];
            float av[4]={a4.x,a4.y,a4.z,a4.w};
            u64 ap[4];
#pragma unroll
            for (int i=0;i<4;i++) PACK2(ap[i], av[i], av[i]);
#pragma unroll
            for (int j4=0;j4<4;j4++){
                float4 b4 = *(const float4*)&Ws[b][kk][j4*64 + tx*4];
                u64 bp0, bp1;
                PACK2(bp0, b4.x, b4.y); PACK2(bp1, b4.z, b4.w);
#pragma unroll
                for (int i=0;i<4;i++){
                    FMA2(acc2[i][j4*2+0], ap[i], bp0, acc2[i][j4*2+0]);
                    FMA2(acc2[i][j4*2+1], ap[i], bp1, acc2[i][j4*2+1]);
                }
            }
        }
        if (t<15) stor((t+1)&1);
        __syncthreads();
    }
    int actm = e % 3;
#pragma unroll
    for (int i=0;i<4;i++){
        int r = ry*4 + i;
        int pr = pairs[r];
        float y[16]; float lsum = 0.f;
#pragma unroll
        for (int h=0;h<8;h++) UNPACK2(y[h*2], y[h*2+1], acc2[i][h]);
#pragma unroll
        for (int j=0;j<16;j++){
            int c = (j>>2)*64 + tx*4 + (j&3);
            y[j] += pb[e*DM + c];
            lsum += y[j];
        }
#pragma unroll
        for (int m=8;m>0;m>>=1) lsum += __shfl_xor_sync(0xffffffffu, lsum, m, 32);
        float mu = lsum * (1.0f/DM);
        float lss = 0.f;
#pragma unroll
        for (int j=0;j<16;j++){ float d=y[j]-mu; lss += d*d; }
#pragma unroll
        for (int m=8;m>0;m>>=1) lss += __shfl_xor_sync(0xffffffffu, lss, m, 32);
        float rstd = rsqrtf(lss*(1.0f/DM) + 1e-5f);
        if (pr >= 0){
            float* orow = g_xpre + (size_t)pr*DM;
#pragma unroll
            for (int j4=0;j4<4;j4++){
                float o[4];
#pragma unroll
                for (int jc=0;jc<4;jc++){
                    int c = j4*64 + tx*4 + jc;
                    float v = (y[j4*4+jc]-mu)*rstd*pg[e*DM+c] + pbb[e*DM+c];
                    o[jc] = (actm==0) ? geluf(v) : (actm==1) ? fmaxf(v,0.f) : tanhf(v);
                }
                *(float4*)&orow[j4*64 + tx*4] = make_float4(o[0],o[1],o[2],o[3]);
            }
        }
    }
}

// ---------------- post experts: 64x256 gathered GEMM + optional LN + weighted scatter, f32x2 ----------------
__global__ __launch_bounds__(256) void post_expert(
    const float* __restrict__ qw, const float* __restrict__ qb,
    const float* __restrict__ qg, const float* __restrict__ qbb,
    float* __restrict__ out_y)
{
    int e = blockIdx.y;
    int cnt = g_cnt[2*NE+e];
    int m0 = blockIdx.x*64;
    if (m0 >= cnt) return;
    __shared__ int pairs[64];
    __shared__ float As[2][16][68];
    __shared__ float Ws[2][16][256];
    int tid = threadIdx.x;
    if (tid < 64) pairs[tid] = (m0+tid < cnt) ? g_list[(2*NE+e)*NPAIR + m0+tid] : -1;
    __syncthreads();
    int arow = tid>>2, ak = (tid&3)*4;
    int prA = pairs[arow];
    const float* Arow = (prA>=0) ? (g_xmlp + (size_t)prA*DM) : 0;
    const float* Wg = qw + (size_t)e*DM*DM;
    int tx = tid&15, ry = tid>>4;

    float4 fa, fw[4];
    auto fetch = [&](int k0){
        fa = Arow ? *(const float4*)(Arow + k0 + ak) : make_float4(0.f,0.f,0.f,0.f);
#pragma unroll
        for (int jj=0;jj<4;jj++){
            int idx = jj*1024 + tid*4;
            fw[jj] = *(const float4*)&Wg[(size_t)(k0+(idx>>8))*DM + (idx&255)];
        }
    };
    auto stor = [&](int b){
        As[b][ak+0][arow]=fa.x; As[b][ak+1][arow]=fa.y; As[b][ak+2][arow]=fa.z; As[b][ak+3][arow]=fa.w;
#pragma unroll
        for (int jj=0;jj<4;jj++){
            int idx = jj*1024 + tid*4;
            *(float4*)&Ws[b][idx>>8][idx&255] = fw[jj];
        }
    };
    fetch(0); stor(0); __syncthreads();
    u64 acc2[4][8] = {};
    for (int t=0;t<16;t++){
        int b = t&1;
        if (t<15) fetch((t+1)*16);
#pragma unroll
        for (int kk=0;kk<16;kk++){
            float4 a4 = *(const float4*)&As[b][kk][ry*4];
            float av[4]={a4.x,a4.y,a4.z,a4.w};
            u64 ap[4];
#pragma unroll
            for (int i=0;i<4;i++) PACK2(ap[i], av[i], av[i]);
#pragma unroll
            for (int j4=0;j4<4;j4++){
                float4 b4 = *(const float4*)&Ws[b][kk][j4*64 + tx*4];
                u64 bp0, bp1;
                PACK2(bp0, b4.x, b4.y); PACK2(bp1, b4.z, b4.w);
#pragma unroll
                for (int i=0;i<4;i++){
                    FMA2(acc2[i][j4*2+0], ap[i], bp0, acc2[i][j4*2+0]);
                    FMA2(acc2[i][j4*2+1], ap[i], bp1, acc2[i][j4*2+1]);
                }
            }
        }
        if (t<15) stor((t+1)&1);
        __syncthreads();
    }
    bool do_ln = ((e & 1) == 0);
#pragma unroll
    for (int i=0;i<4;i++){
        int r = ry*4 + i;
        int pr = pairs[r];
        float y[16];
#pragma unroll
        for (int h=0;h<8;h++) UNPACK2(y[h*2], y[h*2+1], acc2[i][h]);
#pragma unroll
        for (int j=0;j<16;j++){
            int c = (j>>2)*64 + tx*4 + (j&3);
            y[j] += qb[e*DM + c];
        }
        if (do_ln){
            float lsum = 0.f;
#pragma unroll
            for (int j=0;j<16;j++) lsum += y[j];
#pragma unroll
            for (int m=8;m>0;m>>=1) lsum += __shfl_xor_sync(0xffffffffu, lsum, m, 32);
            float mu = lsum * (1.0f/DM);
            float lss = 0.f;
#pragma unroll
            for (int j=0;j<16;j++){ float d=y[j]-mu; lss += d*d; }
#pragma unroll
            for (int m=8;m>0;m>>=1) lss += __shfl_xor_sync(0xffffffffu, lss, m, 32);
            float rstd = rsqrtf(lss*(1.0f/DM) + 1e-5f);
#pragma unroll
            for (int j=0;j<16;j++){
                int c = (j>>2)*64 + tx*4 + (j&3);
                y[j] = (y[j]-mu)*rstd*qg[e*DM+c] + qbb[e*DM+c];
            }
        }
        if (pr >= 0){
            float w = g_topval[pr];
            int tok = pr >> 2;
#pragma unroll
            for (int j=0;j<16;j++){
                int c = (j>>2)*64 + tx*4 + (j&3);
                atomicAdd(&out_y[(size_t)tok*DM + c], y[j]*w);
            }
        }
    }
}

// ---------------- host launch ----------------
extern "C" void kernel_launch(void* const* d_in, const int* in_sizes, int n_in,
                              void* d_out, int out_size)
{
    const float* x   = (const float*)d_in[0];
    const float* rw1 = (const float*)d_in[1];
    const float* rb1 = (const float*)d_in[2];
    const float* rw2 = (const float*)d_in[3];
    const float* rb2 = (const float*)d_in[4];
    const float* rw3 = (const float*)d_in[5];
    const float* rb3 = (const float*)d_in[6];
    const float* temp= (const float*)d_in[7];
    const float* pw  = (const float*)d_in[8];
    const float* pb  = (const float*)d_in[9];
    const float* pg  = (const float*)d_in[10];
    const float* pbb = (const float*)d_in[11];
    const float* mw1 = (const float*)d_in[12];
    const float* mb1 = (const float*)d_in[13];
    const float* mw2 = (const float*)d_in[14];
    const float* mb2 = (const float*)d_in[15];
    const float* qw  = (const float*)d_in[16];
    const float* qb  = (const float*)d_in[17];
    const float* qg  = (const float*)d_in[18];
    const float* qbb = (const float*)d_in[19];

    float* out      = (float*)d_out;
    float* out_y    = out;                     // [N_TOK*DM]
    float* out_loss = out + N_TOK*DM;          // [1]
    float* out_pw   = out + N_TOK*DM + 1;      // [N_TOK*PWY]

    void* p;
    cudaGetSymbolAddress(&p, g_h1);     float* h1 = (float*)p;
    cudaGetSymbolAddress(&p, g_h2);     float* h2 = (float*)p;
    cudaGetSymbolAddress(&p, g_scores); float* scores = (float*)p;
    cudaGetSymbolAddress(&p, g_freq);   float* freqp = (float*)p;
    cudaGetSymbolAddress(&p, g_cnt);    int*   cntp = (int*)p;
    cudaGetSymbolAddress(&p, g_xpre);   float* xpre = (float*)p;
    cudaGetSymbolAddress(&p, g_xmid);   float* xmid = (float*)p;
    cudaGetSymbolAddress(&p, g_xmlp);   float* xmlp = (float*)p;

    cudaMemsetAsync(out_y, 0, (size_t)N_TOK*DM*sizeof(float), 0);
    cudaMemsetAsync(freqp, 0, PWY*sizeof(float), 0);
    cudaMemsetAsync(cntp,  0, 3*NE*sizeof(int), 0);

    // router layers 1,2 (small)
    gemm_plain<<<dim3(256/64, N_TOK/64), 256>>>(x,  rw1, rb1, h1, N_TOK, 256, 256, 1);
    gemm_plain<<<dim3(128/64, N_TOK/64), 256>>>(h1, rw2, rb2, h2, N_TOK, 128, 256, 1);
    // router layer 3 (big): scores = h2 @ rw3 + rb3
    gemm128_g<<<dim3(PWY/128, N_TOK/128, 1), 256>>>(
        h2, 128, rw3, PWY, 0LL, rb3, 0, scores, PWY, 128, 0, 0, 0, -1);

    // softmax + topk + pathway weights + probs writeback
    softmax_topk<<<N_TOK, 256>>>(temp, out_pw);

    // GLBL loss (probs column sums)
    freq_partial<<<dim3(PWY/256, N_TOK/256), 256>>>();
    glbl_loss_kernel<<<1, 256>>>(out_loss);

    // routing
    build_lists<<<NPAIR/256, 256>>>();

    // experts
    pre_expert<<<dim3(NPAIR/64, NE), 256>>>(x, pw, pb, pg, pbb);
    gemm128_g<<<dim3(HMAX/128, NPAIR/128, NE), 256>>>(
        xpre, DM, mw1, HMAX, (long long)DM*HMAX, mb1, HMAX, xmid, HMAX,
        DM, 0, 1, 3, NE);
    gemm128_g<<<dim3(DM/128, NPAIR/128, NE), 256>>>(
        xmid, HMAX, mw2, DM, (long long)HMAX*DM, mb2, DM, xmlp, DM,
        0, 1, 0, 0, NE);
    post_expert<<<dim3(NPAIR/64, NE), 256>>>(qw, qb, qg, qbb, out_y);
}

// round 5
// speedup vs baseline: 1.9514x; 1.3109x over previous
#include <cuda_runtime.h>
#include <cuda_bf16.h>
#include <math.h>

#define N_TOK 2048
#define DM 256
#define PWY 4096
#define KSEL 4
#define NE 16
#define HMAX 1280
#define NPAIR (N_TOK*KSEL)

// packed f32x2 helpers
#define PACK2(out, lo, hi)   asm("mov.b64 %0, {%1, %2};" : "=l"(out) : "f"(lo), "f"(hi))
#define UNPACK2(lo, hi, in)  asm("mov.b64 {%0, %1}, %2;" : "=f"(lo), "=f"(hi) : "l"(in))
#define FMA2(d, a, b, c)     asm("fma.rn.f32x2 %0, %1, %2, %3;" : "=l"(d) : "l"(a), "l"(b), "l"(c))
typedef unsigned long long u64;
typedef unsigned int uint32;

#define MMA_BF16(d, a0,a1,a2,a3, b0,b1) \
  asm volatile("mma.sync.aligned.m16n8k16.row.col.f32.bf16.bf16.f32 " \
    "{%0,%1,%2,%3}, {%4,%5,%6,%7}, {%8,%9}, {%0,%1,%2,%3};" \
    : "+f"(d[0]),"+f"(d[1]),"+f"(d[2]),"+f"(d[3]) \
    : "r"(a0),"r"(a1),"r"(a2),"r"(a3),"r"(b0),"r"(b1))

// ---------------- device scratch (static, no allocation) ----------------
__device__ float g_h1[N_TOK*256];
__device__ float g_h2[N_TOK*128];
__device__ float g_scores[N_TOK*PWY];
__device__ float g_freq[PWY];
__device__ int   g_topidx[NPAIR];
__device__ float g_topval[NPAIR];
__device__ int   g_cnt[3*NE];
__device__ int   g_list[3*NE*NPAIR];
__device__ float g_xpre[NPAIR*DM];
__device__ float g_xmid[(size_t)NPAIR*HMAX];
__device__ float g_xmlp[NPAIR*DM];
// bf16 hi/lo transposed weights: WT[n][k]
__device__ __nv_bfloat16 g_rw3h[PWY*128],  g_rw3l[PWY*128];
__device__ __nv_bfloat16 g_m1h[NE*HMAX*DM], g_m1l[NE*HMAX*DM];
__device__ __nv_bfloat16 g_m2h[NE*DM*HMAX], g_m2l[NE*DM*HMAX];

__device__ __forceinline__ float geluf(float v){
    return 0.5f*v*(1.0f+erff(v*0.70710678118654752f));
}

__device__ __forceinline__ void cvt4(float4 v, uint2& h, uint2& l){
    __nv_bfloat16 h0=__float2bfloat16(v.x), h1=__float2bfloat16(v.y);
    __nv_bfloat16 h2=__float2bfloat16(v.z), h3=__float2bfloat16(v.w);
    __nv_bfloat162 p0(h0,h1), p1(h2,h3);
    h.x = *(uint32*)&p0; h.y = *(uint32*)&p1;
    __nv_bfloat16 l0=__float2bfloat16(v.x-__bfloat162float(h0));
    __nv_bfloat16 l1=__float2bfloat16(v.y-__bfloat162float(h1));
    __nv_bfloat16 l2=__float2bfloat16(v.z-__bfloat162float(h2));
    __nv_bfloat16 l3=__float2bfloat16(v.w-__bfloat162float(h3));
    __nv_bfloat162 q0(l0,l1), q1(l2,l3);
    l.x = *(uint32*)&q0; l.y = *(uint32*)&q1;
}

// ---------------- weight convert + transpose: W[R][C] fp32 -> WT[C][R] bf16 hi/lo ----------------
__global__ __launch_bounds__(256) void convt(
    const float* __restrict__ W, __nv_bfloat16* __restrict__ Th,
    __nv_bfloat16* __restrict__ Tl, int R, int C,
    long long wstride, long long tstride)
{
    int e = blockIdx.z;
    __shared__ float tile[32][33];
    int c0 = blockIdx.x*32, r0 = blockIdx.y*32;
    const float* Win = W + (size_t)e*wstride;
    int tx = threadIdx.x & 31, ty = threadIdx.x >> 5;   // 32 x 8
    for (int i=0;i<32;i+=8)
        tile[ty+i][tx] = Win[(size_t)(r0+ty+i)*C + c0+tx];
    __syncthreads();
    __nv_bfloat16* oh = Th + (size_t)e*tstride;
    __nv_bfloat16* ol = Tl + (size_t)e*tstride;
    for (int i=0;i<32;i+=8){
        float v = tile[tx][ty+i];
        __nv_bfloat16 h = __float2bfloat16(v);
        oh[(size_t)(c0+ty+i)*R + r0+tx] = h;
        ol[(size_t)(c0+ty+i)*R + r0+tx] = __float2bfloat16(v - __bfloat162float(h));
    }
}

// ---------------- small plain GEMM 64x64x16 (router layers 1,2) ----------------
__global__ __launch_bounds__(256) void gemm_plain(
    const float* __restrict__ A, const float* __restrict__ W,
    const float* __restrict__ bias, float* __restrict__ C,
    int M, int Nc, int Ka, int act)
{
    __shared__ float As[16][64];
    __shared__ float Ws[16][64];
    int tid = threadIdx.x;
    int m0 = blockIdx.y*64, n0 = blockIdx.x*64;
    int tx = tid & 15, ty = tid >> 4;
    int lr = tid >> 2, lk = (tid & 3)*4;
    int wr = tid >> 4, wc = (tid & 15)*4;
    u64 acc2[4][2] = {};
    for (int k0 = 0; k0 < Ka; k0 += 16) {
        float4 av = *(const float4*)&A[(size_t)(m0+lr)*Ka + k0 + lk];
        As[lk+0][lr]=av.x; As[lk+1][lr]=av.y; As[lk+2][lr]=av.z; As[lk+3][lr]=av.w;
        *(float4*)&Ws[wr][wc] = *(const float4*)&W[(size_t)(k0+wr)*Nc + n0 + wc];
        __syncthreads();
#pragma unroll
        for (int kk = 0; kk < 16; kk++) {
            float4 a4 = *(const float4*)&As[kk][ty*4];
            float4 b4 = *(const float4*)&Ws[kk][tx*4];
            u64 bp[2];
            PACK2(bp[0], b4.x, b4.y); PACK2(bp[1], b4.z, b4.w);
            float aa[4]={a4.x,a4.y,a4.z,a4.w};
#pragma unroll
            for (int i=0;i<4;i++){
                u64 ap; PACK2(ap, aa[i], aa[i]);
                FMA2(acc2[i][0], ap, bp[0], acc2[i][0]);
                FMA2(acc2[i][1], ap, bp[1], acc2[i][1]);
            }
        }
        __syncthreads();
    }
#pragma unroll
    for (int i=0;i<4;i++){
        int r = m0 + ty*4 + i;
        float a0,a1,a2,a3;
        UNPACK2(a0,a1,acc2[i][0]); UNPACK2(a2,a3,acc2[i][1]);
        float acc[4]={a0,a1,a2,a3};
#pragma unroll
        for (int j=0;j<4;j++){
            int c = n0 + tx*4 + j;
            float v = acc[j] + bias[c];
            if (act==1) v = geluf(v);
            C[(size_t)r*Nc + c] = v;
        }
    }
}

// ---------------- bf16 split-precision tensor-core GEMM: 128x128 tile ----------------
// A fp32 [m][lda] (rows gathered if listoff>=0), WT bf16 hi/lo [n][Kw] per expert.
// C = A*W + bias (fp32 out). act: 0 none, 3 gelu/relu by expert parity.
__global__ __launch_bounds__(256,2) void gemm_bf16(
    const float* __restrict__ A, int lda,
    const __nv_bfloat16* __restrict__ Wth, const __nv_bfloat16* __restrict__ Wtl,
    int Kw, long long wse,
    const float* __restrict__ bias, int bse,
    float* __restrict__ Cout, int ldc,
    int Kfix, int kvar, int nvar, int act, int listoff)
{
    int e = blockIdx.z;
    int hid = DM*(2 + (e>>2));
    int K = kvar ? hid : Kfix;
    int n0 = blockIdx.x*128;
    if (nvar && n0 >= hid) return;
    int m0 = blockIdx.y*128;
    const int* list = 0; int cnt = 0;
    if (listoff >= 0){
        cnt = g_cnt[listoff+e];
        if (m0 >= cnt) return;
        list = g_list + (size_t)(listoff+e)*NPAIR;
    }
    __shared__ int pairs[128];
    __shared__ __nv_bfloat16 Ah[128][40], Al[128][40];
    __shared__ __nv_bfloat16 Bh[128][40], Bl[128][40];
    int tid = threadIdx.x;
    if (tid < 128)
        pairs[tid] = (listoff>=0) ? ((m0+tid < cnt) ? list[m0+tid] : -1) : (m0+tid);
    __syncthreads();

    int arow = tid>>1, akb = (tid&1)*16;
    int prA = pairs[arow];
    const float* Arow = (prA>=0) ? (A + (size_t)prA*lda) : 0;
    const __nv_bfloat16* WThp = Wth + (size_t)e*wse + (size_t)(n0+arow)*Kw;
    const __nv_bfloat16* WTlp = Wtl + (size_t)e*wse + (size_t)(n0+arow)*Kw;

    int lane = tid & 31, wid = tid >> 5;
    int wm = wid >> 2, wn = wid & 3;
    int qr = lane >> 2, qc = lane & 3;

    float acc[4][4][4];
#pragma unroll
    for (int i=0;i<4;i++)
#pragma unroll
    for (int j=0;j<4;j++)
#pragma unroll
    for (int q=0;q<4;q++) acc[i][j][q]=0.f;

    int nchunks = K/32;
    for (int c=0;c<nchunks;c++){
        __syncthreads();
        // A chunk: 128x32 fp32 -> hi/lo bf16
        {
            float4 v[4];
            const float* ap = Arow ? (Arow + c*32 + akb) : 0;
#pragma unroll
            for (int j=0;j<4;j++) v[j] = ap ? *(const float4*)(ap + j*4) : make_float4(0.f,0.f,0.f,0.f);
#pragma unroll
            for (int j=0;j<4;j++){
                uint2 h,l; cvt4(v[j], h, l);
                *(uint2*)&Ah[arow][akb + j*4] = h;
                *(uint2*)&Al[arow][akb + j*4] = l;
            }
        }
        // B chunk: 128 n-rows x 32 k bf16 (already hi/lo in gmem)
        {
            uint4 bh0 = *(const uint4*)(WThp + c*32 + akb);
            uint4 bh1 = *(const uint4*)(WThp + c*32 + akb + 8);
            uint4 bl0 = *(const uint4*)(WTlp + c*32 + akb);
            uint4 bl1 = *(const uint4*)(WTlp + c*32 + akb + 8);
            *(uint2*)&Bh[arow][akb+0]  = make_uint2(bh0.x, bh0.y);
            *(uint2*)&Bh[arow][akb+4]  = make_uint2(bh0.z, bh0.w);
            *(uint2*)&Bh[arow][akb+8]  = make_uint2(bh1.x, bh1.y);
            *(uint2*)&Bh[arow][akb+12] = make_uint2(bh1.z, bh1.w);
            *(uint2*)&Bl[arow][akb+0]  = make_uint2(bl0.x, bl0.y);
            *(uint2*)&Bl[arow][akb+4]  = make_uint2(bl0.z, bl0.w);
            *(uint2*)&Bl[arow][akb+8]  = make_uint2(bl1.x, bl1.y);
            *(uint2*)&Bl[arow][akb+12] = make_uint2(bl1.z, bl1.w);
        }
        __syncthreads();
#pragma unroll
        for (int k16=0;k16<32;k16+=16){
            uint32 bh[4][2], bl[4][2];
#pragma unroll
            for (int nf=0;nf<4;nf++){
                int n = wn*32 + nf*8 + qr;
                bh[nf][0] = *(const uint32*)&Bh[n][k16 + qc*2];
                bh[nf][1] = *(const uint32*)&Bh[n][k16 + qc*2 + 8];
                bl[nf][0] = *(const uint32*)&Bl[n][k16 + qc*2];
                bl[nf][1] = *(const uint32*)&Bl[n][k16 + qc*2 + 8];
            }
#pragma unroll
            for (int mf=0;mf<4;mf++){
                int m = wm*64 + mf*16 + qr;
                uint32 ah0 = *(const uint32*)&Ah[m][k16 + qc*2];
                uint32 ah1 = *(const uint32*)&Ah[m+8][k16 + qc*2];
                uint32 ah2 = *(const uint32*)&Ah[m][k16 + qc*2 + 8];
                uint32 ah3 = *(const uint32*)&Ah[m+8][k16 + qc*2 + 8];
                uint32 al0 = *(const uint32*)&Al[m][k16 + qc*2];
                uint32 al1 = *(const uint32*)&Al[m+8][k16 + qc*2];
                uint32 al2 = *(const uint32*)&Al[m][k16 + qc*2 + 8];
                uint32 al3 = *(const uint32*)&Al[m+8][k16 + qc*2 + 8];
#pragma unroll
                for (int nf=0;nf<4;nf++){
                    MMA_BF16(acc[mf][nf], ah0,ah1,ah2,ah3, bh[nf][0],bh[nf][1]);
                    MMA_BF16(acc[mf][nf], ah0,ah1,ah2,ah3, bl[nf][0],bl[nf][1]);
                    MMA_BF16(acc[mf][nf], al0,al1,al2,al3, bh[nf][0],bh[nf][1]);
                }
            }
        }
    }

    bool relu_e = (act==3) && (e&1);
#pragma unroll
    for (int mf=0;mf<4;mf++){
        int r0 = wm*64 + mf*16 + qr;
        int r1 = r0 + 8;
        int pr0 = pairs[r0], pr1 = pairs[r1];
#pragma unroll
        for (int nf=0;nf<4;nf++){
            int n = n0 + wn*32 + nf*8 + qc*2;
            float b0 = bias[(size_t)e*bse + n];
            float b1 = bias[(size_t)e*bse + n + 1];
            float v00 = acc[mf][nf][0] + b0, v01 = acc[mf][nf][1] + b1;
            float v10 = acc[mf][nf][2] + b0, v11 = acc[mf][nf][3] + b1;
            if (act==3){
                if (relu_e){
                    v00=fmaxf(v00,0.f); v01=fmaxf(v01,0.f);
                    v10=fmaxf(v10,0.f); v11=fmaxf(v11,0.f);
                } else {
                    v00=geluf(v00); v01=geluf(v01);
                    v10=geluf(v10); v11=geluf(v11);
                }
            }
            if (pr0>=0) *(float2*)&Cout[(size_t)pr0*ldc + n] = make_float2(v00,v01);
            if (pr1>=0) *(float2*)&Cout[(size_t)pr1*ldc + n] = make_float2(v10,v11);
        }
    }
}

// ---------------- softmax + topk + pathway_weights + probs writeback ----------------
__global__ __launch_bounds__(256) void softmax_topk(
    const float* __restrict__ temp, float* __restrict__ pwout)
{
    __shared__ float s[PWY];
    __shared__ float rv[256*4];
    __shared__ int   ri[256*4];
    __shared__ float red1[256];
    __shared__ float red2[256];
    __shared__ float pv[KSEL];
    int n = blockIdx.x, tid = threadIdx.x;
    float* srow = g_scores + (size_t)n*PWY;
    for (int i=0;i<4;i++){
        int idx = i*1024 + tid*4;
        *(float4*)&s[idx] = *(const float4*)&srow[idx];
    }
    __syncthreads();
    float invt = 1.0f/temp[0];

    float tv[4] = {-INFINITY,-INFINITY,-INFINITY,-INFINITY};
    int tix[4] = {PWY,PWY,PWY,PWY};
    float lm = -INFINITY;
#pragma unroll
    for (int i=0;i<16;i++){
        int j = tid + i*256;
        float v = s[j];
        lm = fmaxf(lm, v);
        if (v > tv[3] || (v == tv[3] && j < tix[3])){
            tv[3]=v; tix[3]=j;
#pragma unroll
            for (int q=3;q>0;q--){
                if (tv[q] > tv[q-1] || (tv[q]==tv[q-1] && tix[q] < tix[q-1])){
                    float tmv=tv[q]; tv[q]=tv[q-1]; tv[q-1]=tmv;
                    int tmi=tix[q]; tix[q]=tix[q-1]; tix[q-1]=tmi;
                }
            }
        }
    }
    red1[tid]=lm; __syncthreads();
    for (int off=128;off>0;off>>=1){ if(tid<off) red1[tid]=fmaxf(red1[tid],red1[tid+off]); __syncthreads(); }
    float m0 = red1[0]; __syncthreads();

    float f[16]; float ls0=0.f, lst=0.f;
#pragma unroll
    for (int i=0;i<16;i++){
        int j = tid + i*256;
        float d = s[j]-m0;
        float e0 = __expf(d);
        f[i]=e0; ls0+=e0;
        lst += __expf(d*invt);
    }
    red1[tid]=ls0; red2[tid]=lst; __syncthreads();
    for (int off=128;off>0;off>>=1){
        if(tid<off){ red1[tid]+=red1[tid+off]; red2[tid]+=red2[tid+off]; }
        __syncthreads();
    }
    float inv0 = 1.0f/red1[0];
    float invsumt = 1.0f/red2[0];
    __syncthreads();

#pragma unroll
    for (int i=0;i<16;i++) srow[tid + i*256] = f[i]*inv0;

#pragma unroll
    for (int q=0;q<4;q++){ rv[tid*4+q]=tv[q]; ri[tid*4+q]=tix[q]; }
    __syncthreads();
    for (int off=128;off>0;off>>=1){
        if (tid < off){
            float a0[4], b0[4]; int ai[4], bi[4];
#pragma unroll
            for (int q=0;q<4;q++){
                a0[q]=rv[tid*4+q]; ai[q]=ri[tid*4+q];
                b0[q]=rv[(tid+off)*4+q]; bi[q]=ri[(tid+off)*4+q];
            }
            int ia=0, ib=0;
            float ov[4]; int oi[4];
#pragma unroll
            for (int q=0;q<4;q++){
                bool ta = (a0[ia] > b0[ib]) || (a0[ia]==b0[ib] && ai[ia] < bi[ib]);
                if (ta){ ov[q]=a0[ia]; oi[q]=ai[ia]; ia++; }
                else   { ov[q]=b0[ib]; oi[q]=bi[ib]; ib++; }
            }
#pragma unroll
            for (int q=0;q<4;q++){ rv[tid*4+q]=ov[q]; ri[tid*4+q]=oi[q]; }
        }
        __syncthreads();
    }

    if (tid < KSEL){
        int se = ri[tid];
        float p = __expf((s[se]-m0)*invt)*invsumt;
        pv[tid]=p;
        g_topidx[n*KSEL+tid]=se;
        g_topval[n*KSEL+tid]=p;
    }
    __syncthreads();
    float invps = 1.0f/(pv[0]+pv[1]+pv[2]+pv[3] + 1e-8f);
    int s0=ri[0], s1=ri[1], s2=ri[2], s3=ri[3];
    float w0=pv[0]*invps, w1=pv[1]*invps, w2=pv[2]*invps, w3=pv[3]*invps;
    float* prow = pwout + (size_t)n*PWY;
    for (int i=0;i<16;i++){
        int j = tid + i*256;
        float v = 0.f;
        if (j==s0) v=w0; else if (j==s1) v=w1; else if (j==s2) v=w2; else if (j==s3) v=w3;
        prow[j]=v;
    }
}

// ---------------- freq: pure column sums of probs ----------------
__global__ __launch_bounds__(256) void freq_partial()
{
    int p = blockIdx.x*256 + threadIdx.x;
    int nbeg = blockIdx.y*256;
    float acc = 0.f;
    for (int n=nbeg; n<nbeg+256; n++)
        acc += g_scores[(size_t)n*PWY + p];
    atomicAdd(&g_freq[p], acc);
}

__global__ __launch_bounds__(256) void glbl_loss_kernel(float* __restrict__ out)
{
    __shared__ float red[256];
    int tid = threadIdx.x;
    const float invN = 1.0f/(float)N_TOK;
    float lsum = 0.f;
    for (int i=0;i<PWY/256;i++) lsum += g_freq[tid+i*256]*invN;
    red[tid]=lsum; __syncthreads();
    for (int off=128;off>0;off>>=1){ if(tid<off) red[tid]+=red[tid+off]; __syncthreads(); }
    float mean = red[0]/(float)PWY; __syncthreads();
    float lss = 0.f;
    for (int i=0;i<PWY/256;i++){
        float d = g_freq[tid+i*256]*invN - mean;
        lss += d*d;
    }
    red[tid]=lss; __syncthreads();
    for (int off=128;off>0;off>>=1){ if(tid<off) red[tid]+=red[tid+off]; __syncthreads(); }
    if (tid==0) out[0] = (float)PWY * (red[0]/(float)(PWY-1));
}

// ---------------- routing lists ----------------
__global__ __launch_bounds__(256) void build_lists()
{
    int i = blockIdx.x*256 + threadIdx.x;
    if (i >= NPAIR) return;
    int idx = g_topidx[i];
    int pe = idx >> 8, rem = idx & 255;
    int me = rem >> 4, qe = rem & 15;
    int pos;
    pos = atomicAdd(&g_cnt[pe], 1);         g_list[pe*NPAIR + pos] = i;
    pos = atomicAdd(&g_cnt[NE+me], 1);      g_list[(NE+me)*NPAIR + pos] = i;
    pos = atomicAdd(&g_cnt[2*NE+qe], 1);    g_list[(2*NE+qe)*NPAIR + pos] = i;
}

// ---------------- pre experts: 64x256 gathered GEMM + LN + act, f32x2 ----------------
__global__ __launch_bounds__(256) void pre_expert(
    const float* __restrict__ x, const float* __restrict__ pwgt,
    const float* __restrict__ pb, const float* __restrict__ pg,
    const float* __restrict__ pbb)
{
    int e = blockIdx.y;
    int cnt = g_cnt[e];
    int m0 = blockIdx.x*64;
    if (m0 >= cnt) return;
    __shared__ int pairs[64];
    __shared__ float As[2][16][68];
    __shared__ float Ws[2][16][256];
    int tid = threadIdx.x;
    if (tid < 64) pairs[tid] = (m0+tid < cnt) ? g_list[e*NPAIR + m0+tid] : -1;
    __syncthreads();
    int arow = tid>>2, ak = (tid&3)*4;
    int prA = pairs[arow];
    const float* Arow = (prA>=0) ? (x + (size_t)(prA>>2)*DM) : 0;
    const float* Wg = pwgt + (size_t)e*DM*DM;
    int tx = tid&15, ry = tid>>4;

    float4 fa, fw[4];
    auto fetch = [&](int k0){
        fa = Arow ? *(const float4*)(Arow + k0 + ak) : make_float4(0.f,0.f,0.f,0.f);
#pragma unroll
        for (int jj=0;jj<4;jj++){
            int idx = jj*1024 + tid*4;
            fw[jj] = *(const float4*)&Wg[(size_t)(k0+(idx>>8))*DM + (idx&255)];
        }
    };
    auto stor = [&](int b){
        As[b][ak+0][arow]=fa.x; As[b][ak+1][arow]=fa.y; As[b][ak+2][arow]=fa.z; As[b][ak+3][arow]=fa.w;
#pragma unroll
        for (int jj=0;jj<4;jj++){
            int idx = jj*1024 + tid*4;
            *(float4*)&Ws[b][idx>>8][idx&255] = fw[jj];
        }
    };
    fetch(0); stor(0); __syncthreads();
    u64 acc2[4][8] = {};
    for (int t=0;t<16;t++){
        int b = t&1;
        if (t<15) fetch((t+1)*16);
#pragma unroll
        for (int kk=0;kk<16;kk++){
            float4 a4 = *(const float4*)&As[b][kk][ry*4];
            float av[4]={a4.x,a4.y,a4.z,a4.w};
            u64 ap[4];
#pragma unroll
            for (int i=0;i<4;i++) PACK2(ap[i], av[i], av[i]);
#pragma unroll
            for (int j4=0;j4<4;j4++){
                float4 b4 = *(const float4*)&Ws[b][kk][j4*64 + tx*4];
                u64 bp0, bp1;
                PACK2(bp0, b4.x, b4.y); PACK2(bp1, b4.z, b4.w);
#pragma unroll
                for (int i=0;i<4;i++){
                    FMA2(acc2[i][j4*2+0], ap[i], bp0, acc2[i][j4*2+0]);
                    FMA2(acc2[i][j4*2+1], ap[i], bp1, acc2[i][j4*2+1]);
                }
            }
        }
        if (t<15) stor((t+1)&1);
        __syncthreads();
    }
    int actm = e % 3;
#pragma unroll
    for (int i=0;i<4;i++){
        int r = ry*4 + i;
        int pr = pairs[r];
        float y[16]; float lsum = 0.f;
#pragma unroll
        for (int h=0;h<8;h++) UNPACK2(y[h*2], y[h*2+1], acc2[i][h]);
#pragma unroll
        for (int j=0;j<16;j++){
            int c = (j>>2)*64 + tx*4 + (j&3);
            y[j] += pb[e*DM + c];
            lsum += y[j];
        }
#pragma unroll
        for (int m=8;m>0;m>>=1) lsum += __shfl_xor_sync(0xffffffffu, lsum, m, 32);
        float mu = lsum * (1.0f/DM);
        float lss = 0.f;
#pragma unroll
        for (int j=0;j<16;j++){ float d=y[j]-mu; lss += d*d; }
#pragma unroll
        for (int m=8;m>0;m>>=1) lss += __shfl_xor_sync(0xffffffffu, lss, m, 32);
        float rstd = rsqrtf(lss*(1.0f/DM) + 1e-5f);
        if (pr >= 0){
            float* orow = g_xpre + (size_t)pr*DM;
#pragma unroll
            for (int j4=0;j4<4;j4++){
                float o[4];
#pragma unroll
                for (int jc=0;jc<4;jc++){
                    int c = j4*64 + tx*4 + jc;
                    float v = (y[j4*4+jc]-mu)*rstd*pg[e*DM+c] + pbb[e*DM+c];
                    o[jc] = (actm==0) ? geluf(v) : (actm==1) ? fmaxf(v,0.f) : tanhf(v);
                }
                *(float4*)&orow[j4*64 + tx*4] = make_float4(o[0],o[1],o[2],o[3]);
            }
        }
    }
}

// ---------------- post experts: 64x256 gathered GEMM + optional LN + weighted scatter, f32x2 ----------------
__global__ __launch_bounds__(256) void post_expert(
    const float* __restrict__ qw, const float* __restrict__ qb,
    const float* __restrict__ qg, const float* __restrict__ qbb,
    float* __restrict__ out_y)
{
    int e = blockIdx.y;
    int cnt = g_cnt[2*NE+e];
    int m0 = blockIdx.x*64;
    if (m0 >= cnt) return;
    __shared__ int pairs[64];
    __shared__ float As[2][16][68];
    __shared__ float Ws[2][16][256];
    int tid = threadIdx.x;
    if (tid < 64) pairs[tid] = (m0+tid < cnt) ? g_list[(2*NE+e)*NPAIR + m0+tid] : -1;
    __syncthreads();
    int arow = tid>>2, ak = (tid&3)*4;
    int prA = pairs[arow];
    const float* Arow = (prA>=0) ? (g_xmlp + (size_t)prA*DM) : 0;
    const float* Wg = qw + (size_t)e*DM*DM;
    int tx = tid&15, ry = tid>>4;

    float4 fa, fw[4];
    auto fetch = [&](int k0){
        fa = Arow ? *(const float4*)(Arow + k0 + ak) : make_float4(0.f,0.f,0.f,0.f);
#pragma unroll
        for (int jj=0;jj<4;jj++){
            int idx = jj*1024 + tid*4;
            fw[jj] = *(const float4*)&Wg[(size_t)(k0+(idx>>8))*DM + (idx&255)];
        }
    };
    auto stor = [&](int b){
        As[b][ak+0][arow]=fa.x; As[b][ak+1][arow]=fa.y; As[b][ak+2][arow]=fa.z; As[b][ak+3][arow]=fa.w;
#pragma unroll
        for (int jj=0;jj<4;jj++){
            int idx = jj*1024 + tid*4;
            *(float4*)&Ws[b][idx>>8][idx&255] = fw[jj];
        }
    };
    fetch(0); stor(0); __syncthreads();
    u64 acc2[4][8] = {};
    for (int t=0;t<16;t++){
        int b = t&1;
        if (t<15) fetch((t+1)*16);
#pragma unroll
        for (int kk=0;kk<16;kk++){
            float4 a4 = *(const float4*)&As[b][kk][ry*4];
            float av[4]={a4.x,a4.y,a4.z,a4.w};
            u64 ap[4];
#pragma unroll
            for (int i=0;i<4;i++) PACK2(ap[i], av[i], av[i]);
#pragma unroll
            for (int j4=0;j4<4;j4++){
                float4 b4 = *(const float4*)&Ws[b][kk][j4*64 + tx*4];
                u64 bp0, bp1;
                PACK2(bp0, b4.x, b4.y); PACK2(bp1, b4.z, b4.w);
#pragma unroll
                for (int i=0;i<4;i++){
                    FMA2(acc2[i][j4*2+0], ap[i], bp0, acc2[i][j4*2+0]);
                    FMA2(acc2[i][j4*2+1], ap[i], bp1, acc2[i][j4*2+1]);
                }
            }
        }
        if (t<15) stor((t+1)&1);
        __syncthreads();
    }
    bool do_ln = ((e & 1) == 0);
#pragma unroll
    for (int i=0;i<4;i++){
        int r = ry*4 + i;
        int pr = pairs[r];
        float y[16];
#pragma unroll
        for (int h=0;h<8;h++) UNPACK2(y[h*2], y[h*2+1], acc2[i][h]);
#pragma unroll
        for (int j=0;j<16;j++){
            int c = (j>>2)*64 + tx*4 + (j&3);
            y[j] += qb[e*DM + c];
        }
        if (do_ln){
            float lsum = 0.f;
#pragma unroll
            for (int j=0;j<16;j++) lsum += y[j];
#pragma unroll
            for (int m=8;m>0;m>>=1) lsum += __shfl_xor_sync(0xffffffffu, lsum, m, 32);
            float mu = lsum * (1.0f/DM);
            float lss = 0.f;
#pragma unroll
            for (int j=0;j<16;j++){ float d=y[j]-mu; lss += d*d; }
#pragma unroll
            for (int m=8;m>0;m>>=1) lss += __shfl_xor_sync(0xffffffffu, lss, m, 32);
            float rstd = rsqrtf(lss*(1.0f/DM) + 1e-5f);
#pragma unroll
            for (int j=0;j<16;j++){
                int c = (j>>2)*64 + tx*4 + (j&3);
                y[j] = (y[j]-mu)*rstd*qg[e*DM+c] + qbb[e*DM+c];
            }
        }
        if (pr >= 0){
            float w = g_topval[pr];
            int tok = pr >> 2;
#pragma unroll
            for (int j=0;j<16;j++){
                int c = (j>>2)*64 + tx*4 + (j&3);
                atomicAdd(&out_y[(size_t)tok*DM + c], y[j]*w);
            }
        }
    }
}

// ---------------- host launch ----------------
extern "C" void kernel_launch(void* const* d_in, const int* in_sizes, int n_in,
                              void* d_out, int out_size)
{
    const float* x   = (const float*)d_in[0];
    const float* rw1 = (const float*)d_in[1];
    const float* rb1 = (const float*)d_in[2];
    const float* rw2 = (const float*)d_in[3];
    const float* rb2 = (const float*)d_in[4];
    const float* rw3 = (const float*)d_in[5];
    const float* rb3 = (const float*)d_in[6];
    const float* temp= (const float*)d_in[7];
    const float* pw  = (const float*)d_in[8];
    const float* pb  = (const float*)d_in[9];
    const float* pg  = (const float*)d_in[10];
    const float* pbb = (const float*)d_in[11];
    const float* mw1 = (const float*)d_in[12];
    const float* mb1 = (const float*)d_in[13];
    const float* mw2 = (const float*)d_in[14];
    const float* mb2 = (const float*)d_in[15];
    const float* qw  = (const float*)d_in[16];
    const float* qb  = (const float*)d_in[17];
    const float* qg  = (const float*)d_in[18];
    const float* qbb = (const float*)d_in[19];

    float* out      = (float*)d_out;
    float* out_y    = out;
    float* out_loss = out + N_TOK*DM;
    float* out_pw   = out + N_TOK*DM + 1;

    void* p;
    cudaGetSymbolAddress(&p, g_h1);     float* h1 = (float*)p;
    cudaGetSymbolAddress(&p, g_h2);     float* h2 = (float*)p;
    cudaGetSymbolAddress(&p, g_scores); float* scores = (float*)p;
    cudaGetSymbolAddress(&p, g_freq);   float* freqp = (float*)p;
    cudaGetSymbolAddress(&p, g_cnt);    int*   cntp = (int*)p;
    cudaGetSymbolAddress(&p, g_xpre);   float* xpre = (float*)p;
    cudaGetSymbolAddress(&p, g_xmid);   float* xmid = (float*)p;
    cudaGetSymbolAddress(&p, g_xmlp);   float* xmlp = (float*)p;
    cudaGetSymbolAddress(&p, g_rw3h);   __nv_bfloat16* rw3h = (__nv_bfloat16*)p;
    cudaGetSymbolAddress(&p, g_rw3l);   __nv_bfloat16* rw3l = (__nv_bfloat16*)p;
    cudaGetSymbolAddress(&p, g_m1h);    __nv_bfloat16* m1h = (__nv_bfloat16*)p;
    cudaGetSymbolAddress(&p, g_m1l);    __nv_bfloat16* m1l = (__nv_bfloat16*)p;
    cudaGetSymbolAddress(&p, g_m2h);    __nv_bfloat16* m2h = (__nv_bfloat16*)p;
    cudaGetSymbolAddress(&p, g_m2l);    __nv_bfloat16* m2l = (__nv_bfloat16*)p;

    cudaMemsetAsync(out_y, 0, (size_t)N_TOK*DM*sizeof(float), 0);
    cudaMemsetAsync(freqp, 0, PWY*sizeof(float), 0);
    cudaMemsetAsync(cntp,  0, 3*NE*sizeof(int), 0);

    // weight conversion + transpose (bf16 hi/lo)
    convt<<<dim3(PWY/32, 128/32, 1), 256>>>(rw3, rw3h, rw3l, 128, PWY, 0LL, 0LL);
    convt<<<dim3(HMAX/32, DM/32, NE), 256>>>(mw1, m1h, m1l, DM, HMAX,
        (long long)DM*HMAX, (long long)HMAX*DM);
    convt<<<dim3(DM/32, HMAX/32, NE), 256>>>(mw2, m2h, m2l, HMAX, DM,
        (long long)HMAX*DM, (long long)DM*HMAX);

    // router layers 1,2 (small, fp32)
    gemm_plain<<<dim3(256/64, N_TOK/64), 256>>>(x,  rw1, rb1, h1, N_TOK, 256, 256, 1);
    gemm_plain<<<dim3(128/64, N_TOK/64), 256>>>(h1, rw2, rb2, h2, N_TOK, 128, 256, 1);
    // router layer 3: scores = h2 @ rw3 + rb3 (bf16 split tensor core)
    gemm_bf16<<<dim3(PWY/128, N_TOK/128, 1), 256>>>(
        h2, 128, rw3h, rw3l, 128, 0LL, rb3, 0, scores, PWY,
        128, 0, 0, 0, -1);

    // softmax + topk + pathway weights + probs writeback
    softmax_topk<<<N_TOK, 256>>>(temp, out_pw);

    // GLBL loss
    freq_partial<<<dim3(PWY/256, N_TOK/256), 256>>>();
    glbl_loss_kernel<<<1, 256>>>(out_loss);

    // routing
    build_lists<<<NPAIR/256, 256>>>();

    // experts
    pre_expert<<<dim3(NPAIR/64, NE), 256>>>(x, pw, pb, pg, pbb);
    gemm_bf16<<<dim3(HMAX/128, NPAIR/128, NE), 256>>>(
        xpre, DM, m1h, m1l, DM, (long long)HMAX*DM, mb1, HMAX, xmid, HMAX,
        DM, 0, 1, 3, NE);
    gemm_bf16<<<dim3(DM/128, NPAIR/128, NE), 256>>>(
        xmid, HMAX, m2h, m2l, HMAX, (long long)DM*HMAX, mb2, DM, xmlp, DM,
        0, 1, 0, 0, NE);
    post_expert<<<dim3(NPAIR/64, NE), 256>>>(qw, qb, qg, qbb, out_y);
}